// round 1
// baseline (speedup 1.0000x reference)
#include <cuda_runtime.h>
#include <math.h>

#define NB   8          // batch
#define HSP  37         // spatial H
#define WSP  37         // spatial W
#define NPIX 1369       // H*W
#define BN   10952      // B * N
#define CC   1024       // channels
#define HEADS 8
#define HD   128        // head dim
#define PTS  8          // sample points

// Scratch (static device globals: allocation-free per harness rules)
__device__ float g_q[BN * CC];            // 44.9 MB
__device__ float g_k[BN * CC];            // 44.9 MB
__device__ float g_off[BN * HEADS * PTS * 2]; // 5.6 MB
__device__ float g_attn[BN * CC];         // 44.9 MB

// ---------------------------------------------------------------------------
// Tiled SGEMM with bias: C[M,Ncols] = A[M,K] @ W[K,ldw][:, :Ncols] + bias
// 64x64 tile, K-tile 16, 256 threads, 4x4 micro-tile per thread.
// ---------------------------------------------------------------------------
__global__ void sgemm_bias_kernel(const float* __restrict__ A,
                                  const float* __restrict__ Wt,
                                  const float* __restrict__ bias,
                                  float* __restrict__ C,
                                  int M, int Ncols, int K, int ldw)
{
    __shared__ float As[16][64];
    __shared__ float Bs[16][64];

    const int tid = threadIdx.x;
    const int tx = tid & 15;        // 0..15 -> column group
    const int ty = tid >> 4;        // 0..15 -> row group
    const int n0 = blockIdx.x * 64;
    const int m0 = blockIdx.y * 64;

    float acc[4][4] = {};

    for (int k0 = 0; k0 < K; k0 += 16) {
        // Load A tile: 64 rows x 16 k
        #pragma unroll
        for (int i = 0; i < 4; i++) {
            int idx = tid + i * 256;
            int m  = idx >> 4;
            int kk = idx & 15;
            int gm = m0 + m;
            As[kk][m] = (gm < M) ? A[(size_t)gm * K + (k0 + kk)] : 0.0f;
        }
        // Load W tile: 16 k x 64 cols (row stride ldw)
        #pragma unroll
        for (int i = 0; i < 4; i++) {
            int idx = tid + i * 256;
            int kk = idx >> 6;
            int n  = idx & 63;
            int gn = n0 + n;
            Bs[kk][n] = (gn < Ncols) ? Wt[(size_t)(k0 + kk) * ldw + gn] : 0.0f;
        }
        __syncthreads();

        #pragma unroll
        for (int kk = 0; kk < 16; kk++) {
            float4 a = *(const float4*)&As[kk][ty * 4];
            float4 w = *(const float4*)&Bs[kk][tx * 4];
            acc[0][0] += a.x * w.x; acc[0][1] += a.x * w.y; acc[0][2] += a.x * w.z; acc[0][3] += a.x * w.w;
            acc[1][0] += a.y * w.x; acc[1][1] += a.y * w.y; acc[1][2] += a.y * w.z; acc[1][3] += a.y * w.w;
            acc[2][0] += a.z * w.x; acc[2][1] += a.z * w.y; acc[2][2] += a.z * w.z; acc[2][3] += a.z * w.w;
            acc[3][0] += a.w * w.x; acc[3][1] += a.w * w.y; acc[3][2] += a.w * w.z; acc[3][3] += a.w * w.w;
        }
        __syncthreads();
    }

    #pragma unroll
    for (int r = 0; r < 4; r++) {
        int gm = m0 + ty * 4 + r;
        if (gm >= M) continue;
        #pragma unroll
        for (int c = 0; c < 4; c++) {
            int gn = n0 + tx * 4 + c;
            if (gn < Ncols)
                C[(size_t)gm * Ncols + gn] = acc[r][c] + bias[gn];
        }
    }
}

// ---------------------------------------------------------------------------
// Deformable attention: one block per (b*n, head), 128 threads = hd channels.
// Bilinear-gathers 8 points from g_k (border clamp, align_corners=True),
// dot-products with q, softmaxes over the 8 points, weighted-sums.
// Matches the reference exactly: x_norm = y_lin(row)+off0, y_norm = x_lin(col)+off1,
// gather index = iy*W + ix with ix from x_norm, iy from y_norm.
// ---------------------------------------------------------------------------
__global__ void attn_kernel(float* __restrict__ out)
{
    const int bn = blockIdx.x;          // 0..BN-1
    const int h  = blockIdx.y;          // 0..7
    const int t  = threadIdx.x;         // 0..127 (channel within head)
    const int lane = t & 31;
    const int wid  = t >> 5;

    const int b = bn / NPIX;
    const int n = bn % NPIX;
    const int row = n / WSP;
    const int col = n % WSP;

    const float step = 2.0f / 36.0f;
    const float ybase = -1.0f + row * step;   // coords[...,0] (from linspace over H)
    const float xbase = -1.0f + col * step;   // coords[...,1] (from linspace over W)

    const float qv = g_q[(size_t)bn * CC + h * HD + t];
    const float* kbase = g_k + (size_t)b * NPIX * CC + h * HD + t;
    const float* offp  = g_off + (size_t)bn * (HEADS * PTS * 2) + h * (PTS * 2);

    float sv[PTS];
    __shared__ float red[PTS][4];
    __shared__ float sc[PTS];

    #pragma unroll
    for (int p = 0; p < PTS; p++) {
        float o0 = offp[p * 2 + 0];
        float o1 = offp[p * 2 + 1];
        float xn = ybase + o0;   // locs[...,0] -> x_norm arg
        float yn = xbase + o1;   // locs[...,1] -> y_norm arg

        float ix = fminf(fmaxf((xn + 1.0f) * 0.5f * (WSP - 1), 0.0f), (float)(WSP - 1));
        float iy = fminf(fmaxf((yn + 1.0f) * 0.5f * (HSP - 1), 0.0f), (float)(HSP - 1));
        float x0f = floorf(ix);
        float y0f = floorf(iy);
        float wx = ix - x0f;
        float wy = iy - y0f;
        int x0 = (int)x0f;
        int y0 = (int)y0f;
        int x1 = min(x0 + 1, WSP - 1);
        int y1 = min(y0 + 1, HSP - 1);

        float v00 = kbase[(size_t)(y0 * WSP + x0) * CC];
        float v01 = kbase[(size_t)(y0 * WSP + x1) * CC];
        float v10 = kbase[(size_t)(y1 * WSP + x0) * CC];
        float v11 = kbase[(size_t)(y1 * WSP + x1) * CC];

        float s = (1.0f - wy) * ((1.0f - wx) * v00 + wx * v01)
                +          wy * ((1.0f - wx) * v10 + wx * v11);
        sv[p] = s;

        // cross-channel dot product with q (128-wide reduction)
        float d = qv * s;
        #pragma unroll
        for (int o = 16; o; o >>= 1)
            d += __shfl_down_sync(0xffffffffu, d, o);
        if (lane == 0) red[p][wid] = d;
    }
    __syncthreads();

    if (t < PTS) {
        const float scale = 0.088388347648318447f;  // 128^-0.5
        sc[t] = (red[t][0] + red[t][1] + red[t][2] + red[t][3]) * scale;
    }
    __syncthreads();

    // softmax over 8 points (every thread computes locally from smem broadcast)
    float m = sc[0];
    #pragma unroll
    for (int p = 1; p < PTS; p++) m = fmaxf(m, sc[p]);
    float e[PTS];
    float denom = 0.0f;
    #pragma unroll
    for (int p = 0; p < PTS; p++) { e[p] = expf(sc[p] - m); denom += e[p]; }
    float inv = 1.0f / denom;

    float o = 0.0f;
    #pragma unroll
    for (int p = 0; p < PTS; p++) o += e[p] * inv * sv[p];

    out[(size_t)bn * CC + h * HD + t] = o;
}

// ---------------------------------------------------------------------------
// Launch
// ---------------------------------------------------------------------------
extern "C" void kernel_launch(void* const* d_in, const int* in_sizes, int n_in,
                              void* d_out, int out_size)
{
    const float* query = (const float*)d_in[0];
    const float* ref   = (const float*)d_in[1];
    const float* Wq    = (const float*)d_in[2];
    const float* bq    = (const float*)d_in[3];
    const float* Wkv   = (const float*)d_in[4];
    const float* bkv   = (const float*)d_in[5];
    const float* Woff  = (const float*)d_in[6];
    const float* boff  = (const float*)d_in[7];
    const float* Wout  = (const float*)d_in[8];
    const float* bout  = (const float*)d_in[9];
    float* out = (float*)d_out;

    float *q_ptr, *k_ptr, *off_ptr, *attn_ptr;
    cudaGetSymbolAddress((void**)&q_ptr,    g_q);
    cudaGetSymbolAddress((void**)&k_ptr,    g_k);
    cudaGetSymbolAddress((void**)&off_ptr,  g_off);
    cudaGetSymbolAddress((void**)&attn_ptr, g_attn);

    dim3 blk(256);
    dim3 gBig((CC + 63) / 64, (BN + 63) / 64);      // 16 x 172
    dim3 gOff((128 + 63) / 64, (BN + 63) / 64);     //  2 x 172

    // q = query @ Wq + bq
    sgemm_bias_kernel<<<gBig, blk>>>(query, Wq, bq, q_ptr, BN, CC, CC, CC);
    // k = ref @ Wkv[:, :C] + bkv[:C]   (v is unused by the reference)
    sgemm_bias_kernel<<<gBig, blk>>>(ref, Wkv, bkv, k_ptr, BN, CC, CC, 2 * CC);
    // off = query @ Woff + boff
    sgemm_bias_kernel<<<gOff, blk>>>(query, Woff, boff, off_ptr, BN, HEADS * PTS * 2, CC, HEADS * PTS * 2);

    // deformable attention -> g_attn
    dim3 gAttn(BN, HEADS);
    attn_kernel<<<gAttn, 128>>>(attn_ptr);

    // out = attn @ Wout + bout
    sgemm_bias_kernel<<<gBig, blk>>>(attn_ptr, Wout, bout, out, BN, CC, CC, CC);
}

// round 3
// speedup vs baseline: 3.5530x; 3.5530x over previous
#include <cuda_runtime.h>
#include <cuda_bf16.h>
#include <cstdint>
#include <math.h>

#define NB   8
#define HSP  37
#define WSP  37
#define NPIX 1369
#define BN   10952
#define CC   1024
#define HEADS 8
#define HD   128
#define PTS  8

// tcgen05 only exists on arch-specific ('a') targets. One harness compile pass
// targets plain sm_103, which rejects every tcgen05 op — so the tensor path is
// compiled only when the arch-specific feature macros are present, and the host
// dispatches at runtime based on which body got loaded.
#if defined(__CUDA_ARCH__) && (defined(__CUDA_ARCH_FEAT_SM103_ALL) || defined(__CUDA_ARCH_FEAT_SM100_ALL) || defined(__CUDA_ARCH_SPECIFIC__))
#define HAS_TCGEN05 1
#else
#define HAS_TCGEN05 0
#endif

// ============================ Scratch ============================
__device__ float g_q[BN * CC];
__device__ float g_k[BN * CC];
__device__ float g_off[BN * HEADS * PTS * 2];
__device__ float g_attn[BN * CC];

__device__ __nv_bfloat16 g_qh[BN * CC];
__device__ __nv_bfloat16 g_ql[BN * CC];
__device__ __nv_bfloat16 g_rh[BN * CC];
__device__ __nv_bfloat16 g_rl[BN * CC];
__device__ __nv_bfloat16 g_ah[BN * CC];
__device__ __nv_bfloat16 g_al[BN * CC];
__device__ __nv_bfloat16 g_WqT_h[CC * CC];
__device__ __nv_bfloat16 g_WqT_l[CC * CC];
__device__ __nv_bfloat16 g_WkT_h[CC * CC];
__device__ __nv_bfloat16 g_WkT_l[CC * CC];
__device__ __nv_bfloat16 g_WoT_h[CC * CC];
__device__ __nv_bfloat16 g_WoT_l[CC * CC];
__device__ __nv_bfloat16 g_WoffT_h[128 * CC];
__device__ __nv_bfloat16 g_WoffT_l[128 * CC];

// ============================ PTX helpers (guarded) ============================
#if HAS_TCGEN05
__device__ __forceinline__ uint32_t smem_to_u32(const void* p) {
    uint32_t a;
    asm("{ .reg .u64 t; cvta.to.shared.u64 t, %1; cvt.u32.u64 %0, t; }" : "=r"(a) : "l"(p));
    return a;
}
__device__ __forceinline__ uint32_t elect_one_pred() {
    uint32_t pred;
    asm volatile("{\n\t.reg .pred p;\n\telect.sync _|p, 0xFFFFFFFF;\n\tselp.b32 %0, 1, 0, p;\n\t}" : "=r"(pred));
    return pred;
}
#define TCGEN05_ALLOC(smem_result_addr, nCols) \
    asm volatile("tcgen05.alloc.cta_group::1.sync.aligned.shared::cta.b32 [%0], %1;" \
        :: "r"((uint32_t)(smem_result_addr)), "r"((uint32_t)(nCols)) : "memory")
#define TCGEN05_DEALLOC(tmem_addr, nCols) \
    asm volatile("tcgen05.dealloc.cta_group::1.sync.aligned.b32 %0, %1;" :: "r"(tmem_addr), "r"(nCols))
#define TCGEN05_RELINQUISH_ALLOC_PERMIT() \
    asm volatile("tcgen05.relinquish_alloc_permit.cta_group::1.sync.aligned;")
#define TCGEN05_COMMIT(mbar_smem_addr) \
    asm volatile("tcgen05.commit.cta_group::1.mbarrier::arrive::one.shared::cluster.b64 [%0];" \
        :: "r"((uint32_t)(mbar_smem_addr)) : "memory")
#define TCGEN05_WAIT_LD() asm volatile("tcgen05.wait::ld.sync.aligned;" ::: "memory")
#define TCGEN05_FENCE_AFTER() asm volatile("tcgen05.fence::after_thread_sync;" ::: "memory")
#define TCGEN05_FENCE_BEFORE() asm volatile("tcgen05.fence::before_thread_sync;" ::: "memory")
#define FENCE_PROXY_ASYNC_SHARED_CTA() asm volatile("fence.proxy.async.shared::cta;" ::: "memory")
#define MBARRIER_INIT(mbar_smem_addr, count) \
    asm volatile("mbarrier.init.shared.b64 [%0], %1;" \
        :: "r"((uint32_t)(mbar_smem_addr)), "r"((uint32_t)(count)) : "memory")
#define MBARRIER_WAIT_PARITY(mbar_smem_addr, phase_parity) do { \
    uint32_t _mbar = (uint32_t)(mbar_smem_addr); \
    uint32_t _parity = (uint32_t)(phase_parity); \
    uint32_t _done; \
    asm volatile("{\n\t.reg .pred p;\n\t" \
        "mbarrier.try_wait.parity.acquire.cta.shared::cta.b64 p, [%1], %2;\n\t" \
        "selp.b32 %0, 1, 0, p;\n\t}" : "=r"(_done) : "r"(_mbar), "r"(_parity) : "memory"); \
    if (!_done) { \
        asm volatile("{\n\t.reg .pred P1;\n\t" \
            "WAIT_LOOP_%=:\n\t" \
            "mbarrier.try_wait.parity.acquire.cta.shared::cta.b64 P1, [%0], %1, 0x989680;\n\t" \
            "@P1 bra.uni WAIT_DONE_%=;\n\t" \
            "bra.uni WAIT_LOOP_%=;\n\t" \
            "WAIT_DONE_%=:\n\t}" :: "r"(_mbar), "r"(_parity) : "memory"); \
    } \
} while(0)
#define STS128(r0, r1, r2, r3, smem_addr) \
    asm volatile("st.shared.v4.b32 [%0], {%1, %2, %3, %4};" \
        :: "r"(smem_addr), "r"(r0), "r"(r1), "r"(r2), "r"(r3) : "memory")
#define TCGEN05_LD_32X32B_X32(r, tmem_addr) \
    asm volatile("tcgen05.ld.sync.aligned.32x32b.x32.b32 " \
        "{%0, %1, %2, %3, %4, %5, %6, %7, %8, %9, %10, %11, %12, %13, %14, %15, " \
        " %16, %17, %18, %19, %20, %21, %22, %23, %24, %25, %26, %27, %28, %29, %30, %31}, [%32];" \
        : "=r"((r)[0]),  "=r"((r)[1]),  "=r"((r)[2]),  "=r"((r)[3]), \
          "=r"((r)[4]),  "=r"((r)[5]),  "=r"((r)[6]),  "=r"((r)[7]), \
          "=r"((r)[8]),  "=r"((r)[9]),  "=r"((r)[10]), "=r"((r)[11]), \
          "=r"((r)[12]), "=r"((r)[13]), "=r"((r)[14]), "=r"((r)[15]), \
          "=r"((r)[16]), "=r"((r)[17]), "=r"((r)[18]), "=r"((r)[19]), \
          "=r"((r)[20]), "=r"((r)[21]), "=r"((r)[22]), "=r"((r)[23]), \
          "=r"((r)[24]), "=r"((r)[25]), "=r"((r)[26]), "=r"((r)[27]), \
          "=r"((r)[28]), "=r"((r)[29]), "=r"((r)[30]), "=r"((r)[31]) \
        : "r"(tmem_addr))

static constexpr uint64_t SMEM_DESC_BASE_SW128 =
    (uint64_t(2)  << 61) | (uint64_t(1) << 46) | (uint64_t(64) << 32) | (uint64_t(1) << 16);
#define MAKE_SMEM_DESC(base_addr) (SMEM_DESC_BASE_SW128 | ((uint64_t)((base_addr) >> 4) & 0x3FFF))

__device__ __forceinline__ void mma_f16_ss(uint32_t d, uint64_t ad, uint64_t bd,
                                           uint32_t idesc, bool en) {
    uint32_t e = en ? 1u : 0u;
    asm volatile(
        "{\n\t.reg .pred p;\n\tsetp.ne.u32 p, %5, 0;\n\t"
        "tcgen05.mma.cta_group::1.kind::f16 [%0], %1, %2, %3, {%4, %4, %4, %4}, p;\n\t}"
        :: "r"(d), "l"(ad), "l"(bd), "r"(idesc), "r"(0u), "r"(e) : "memory");
}
#endif  // HAS_TCGEN05

#define SMEM_SWIZZLE_128B(byte_offset) ((byte_offset) ^ (((byte_offset) >> 3) & 0x70))

// ============================ Converters ============================
__global__ void split_kernel(const float* __restrict__ src,
                             __nv_bfloat16* __restrict__ hi,
                             __nv_bfloat16* __restrict__ lo, int n)
{
    int i = blockIdx.x * blockDim.x + threadIdx.x;
    int stride = gridDim.x * blockDim.x;
    for (; i < n; i += stride) {
        float x = src[i];
        __nv_bfloat16 h = __float2bfloat16(x);
        hi[i] = h;
        lo[i] = __float2bfloat16(x - __bfloat162float(h));
    }
}

__global__ void tsplit_kernel(const float* __restrict__ W,
                              __nv_bfloat16* __restrict__ hiT,
                              __nv_bfloat16* __restrict__ loT,
                              int K, int N, int ldw)
{
    __shared__ float t[32][33];
    int k0 = blockIdx.y * 32, n0 = blockIdx.x * 32;
    int tx = threadIdx.x, ty = threadIdx.y;
    t[ty][tx] = W[(size_t)(k0 + ty) * ldw + n0 + tx];
    __syncthreads();
    float x = t[tx][ty];
    __nv_bfloat16 h = __float2bfloat16(x);
    size_t o = (size_t)(n0 + ty) * K + k0 + tx;
    hiT[o] = h;
    loT[o] = __float2bfloat16(x - __bfloat162float(h));
}

// ============================ tcgen05 GEMM ============================
#define GK 1024
#define CHUNK 64
#define NCH 16
#define STAGES 3
#define PART_BYTES 16384
#define STAGE_BYTES (4 * PART_BYTES)
#define SM_HDR 1024
#define GEMM_SMEM (SM_HDR + STAGES * STAGE_BYTES)

__global__ void __launch_bounds__(128, 1)
gemm_tc(const __nv_bfloat16* __restrict__ Ah, const __nv_bfloat16* __restrict__ Al,
        const __nv_bfloat16* __restrict__ Bh, const __nv_bfloat16* __restrict__ Bl,
        const float* __restrict__ bias, float* __restrict__ C, int M, int Ncols)
{
#if HAS_TCGEN05
    extern __shared__ char smem[];
    uint32_t sb = smem_to_u32(smem);
    const int tid = threadIdx.x;
    const int wid = tid >> 5;
    const int lane = tid & 31;
    const int m0 = blockIdx.y * 128;
    const int n0 = blockIdx.x * 128;

    if (wid == 0) TCGEN05_ALLOC(sb + 0, 128);
    if (tid == 0) {
        MBARRIER_INIT(sb + 16, 1);
        MBARRIER_INIT(sb + 24, 1);
        MBARRIER_INIT(sb + 32, 1);
    }
    __syncthreads();
    uint32_t tmem;
    asm volatile("ld.shared.b32 %0, [%1];" : "=r"(tmem) : "r"(sb));

    int wph[STAGES] = {0, 0, 0};
    const uint32_t idesc = 0x8200490u;  // F32 acc, bf16xbf16, M=128, N=128

    for (int c = 0; c < NCH; c++) {
        const int s = c % STAGES;
        const uint32_t mbar = sb + 16 + 8u * s;
        if (c >= STAGES) {
            MBARRIER_WAIT_PARITY(mbar, (uint32_t)(wph[s] & 1));
            wph[s]++;
        }
        const uint32_t tb = sb + SM_HDR + (uint32_t)s * STAGE_BYTES;
        const int k0 = c * CHUNK;

        #pragma unroll
        for (int i = 0; i < 8; i++) {
            int idx = tid + i * 128;
            int m = idx >> 3, j = idx & 7;
            size_t koff = (size_t)(k0 + j * 8);
            uint32_t soff = SMEM_SWIZZLE_128B((uint32_t)(m * 128 + j * 16));
            int gm = m0 + m;
            uint4 va = make_uint4(0, 0, 0, 0), vla = va;
            if (gm < M) {
                va  = *(const uint4*)(Ah + (size_t)gm * GK + koff);
                vla = *(const uint4*)(Al + (size_t)gm * GK + koff);
            }
            STS128(va.x, va.y, va.z, va.w, tb + soff);
            STS128(vla.x, vla.y, vla.z, vla.w, tb + PART_BYTES + soff);
            int gn = n0 + m;
            uint4 wh = *(const uint4*)(Bh + (size_t)gn * GK + koff);
            uint4 wl = *(const uint4*)(Bl + (size_t)gn * GK + koff);
            STS128(wh.x, wh.y, wh.z, wh.w, tb + 2 * PART_BYTES + soff);
            STS128(wl.x, wl.y, wl.z, wl.w, tb + 3 * PART_BYTES + soff);
        }
        FENCE_PROXY_ASYNC_SHARED_CTA();
        __syncthreads();

        if (wid == 0 && elect_one_pred()) {
            uint64_t a0 = MAKE_SMEM_DESC(tb);
            uint64_t a1 = MAKE_SMEM_DESC(tb + PART_BYTES);
            uint64_t b0 = MAKE_SMEM_DESC(tb + 2 * PART_BYTES);
            uint64_t b1 = MAKE_SMEM_DESC(tb + 3 * PART_BYTES);
            #pragma unroll
            for (int ks = 0; ks < 4; ks++)
                mma_f16_ss(tmem, a0 + ks * 2, b0 + ks * 2, idesc, !(c == 0 && ks == 0));
            #pragma unroll
            for (int ks = 0; ks < 4; ks++)
                mma_f16_ss(tmem, a0 + ks * 2, b1 + ks * 2, idesc, true);
            #pragma unroll
            for (int ks = 0; ks < 4; ks++)
                mma_f16_ss(tmem, a1 + ks * 2, b0 + ks * 2, idesc, true);
            TCGEN05_COMMIT(mbar);
        }
    }

    for (int c = NCH - STAGES; c < NCH; c++) {
        int s = c % STAGES;
        MBARRIER_WAIT_PARITY(sb + 16 + 8u * s, (uint32_t)(wph[s] & 1));
        wph[s]++;
    }
    TCGEN05_FENCE_AFTER();

    const int gm = m0 + wid * 32 + lane;
    #pragma unroll
    for (int base = 0; base < 128; base += 32) {
        uint32_t r[32];
        TCGEN05_LD_32X32B_X32(r, tmem + base);
        TCGEN05_WAIT_LD();
        if (gm < M) {
            #pragma unroll
            for (int q = 0; q < 32; q++)
                C[(size_t)gm * Ncols + n0 + base + q] = __uint_as_float(r[q]) + bias[n0 + base + q];
        }
    }
    TCGEN05_FENCE_BEFORE();
    __syncthreads();
    if (wid == 0) {
        TCGEN05_RELINQUISH_ALLOC_PERMIT();
        TCGEN05_DEALLOC(tmem, 128);
    }
#endif  // HAS_TCGEN05 (plain-arch pass compiles an empty stub; host dispatch avoids it)
}

// ============================ Fallback SGEMM (always compiled) ============================
__global__ void sgemm_bias_kernel(const float* __restrict__ A,
                                  const float* __restrict__ Wt,
                                  const float* __restrict__ bias,
                                  float* __restrict__ C,
                                  int M, int Ncols, int K, int ldw)
{
    __shared__ float As[16][64];
    __shared__ float Bs[16][64];

    const int tid = threadIdx.x;
    const int tx = tid & 15;
    const int ty = tid >> 4;
    const int n0 = blockIdx.x * 64;
    const int m0 = blockIdx.y * 64;

    float acc[4][4] = {};

    for (int k0 = 0; k0 < K; k0 += 16) {
        #pragma unroll
        for (int i = 0; i < 4; i++) {
            int idx = tid + i * 256;
            int m  = idx >> 4;
            int kk = idx & 15;
            int gm = m0 + m;
            As[kk][m] = (gm < M) ? A[(size_t)gm * K + (k0 + kk)] : 0.0f;
        }
        #pragma unroll
        for (int i = 0; i < 4; i++) {
            int idx = tid + i * 256;
            int kk = idx >> 6;
            int n  = idx & 63;
            int gn = n0 + n;
            Bs[kk][n] = (gn < Ncols) ? Wt[(size_t)(k0 + kk) * ldw + gn] : 0.0f;
        }
        __syncthreads();

        #pragma unroll
        for (int kk = 0; kk < 16; kk++) {
            float4 a = *(const float4*)&As[kk][ty * 4];
            float4 w = *(const float4*)&Bs[kk][tx * 4];
            acc[0][0] += a.x * w.x; acc[0][1] += a.x * w.y; acc[0][2] += a.x * w.z; acc[0][3] += a.x * w.w;
            acc[1][0] += a.y * w.x; acc[1][1] += a.y * w.y; acc[1][2] += a.y * w.z; acc[1][3] += a.y * w.w;
            acc[2][0] += a.z * w.x; acc[2][1] += a.z * w.y; acc[2][2] += a.z * w.z; acc[2][3] += a.z * w.w;
            acc[3][0] += a.w * w.x; acc[3][1] += a.w * w.y; acc[3][2] += a.w * w.z; acc[3][3] += a.w * w.w;
        }
        __syncthreads();
    }

    #pragma unroll
    for (int r = 0; r < 4; r++) {
        int gm = m0 + ty * 4 + r;
        if (gm >= M) continue;
        #pragma unroll
        for (int c = 0; c < 4; c++) {
            int gn = n0 + tx * 4 + c;
            if (gn < Ncols)
                C[(size_t)gm * Ncols + gn] = acc[r][c] + bias[gn];
        }
    }
}

// ============================ Attention ============================
__global__ void attn_kernel(float* __restrict__ out)
{
    const int bn = blockIdx.x;
    const int h  = blockIdx.y;
    const int t  = threadIdx.x;
    const int lane = t & 31;
    const int wid  = t >> 5;

    const int b = bn / NPIX;
    const int n = bn % NPIX;
    const int row = n / WSP;
    const int col = n % WSP;

    const float step = 2.0f / 36.0f;
    const float ybase = -1.0f + row * step;
    const float xbase = -1.0f + col * step;

    const float qv = g_q[(size_t)bn * CC + h * HD + t];
    const float* kbase = g_k + (size_t)b * NPIX * CC + h * HD + t;
    const float* offp  = g_off + (size_t)bn * (HEADS * PTS * 2) + h * (PTS * 2);

    float sv[PTS];
    __shared__ float red[PTS][4];
    __shared__ float sc[PTS];

    #pragma unroll
    for (int p = 0; p < PTS; p++) {
        float o0 = offp[p * 2 + 0];
        float o1 = offp[p * 2 + 1];
        float xn = ybase + o0;
        float yn = xbase + o1;

        float ix = fminf(fmaxf((xn + 1.0f) * 0.5f * (WSP - 1), 0.0f), (float)(WSP - 1));
        float iy = fminf(fmaxf((yn + 1.0f) * 0.5f * (HSP - 1), 0.0f), (float)(HSP - 1));
        float x0f = floorf(ix);
        float y0f = floorf(iy);
        float wx = ix - x0f;
        float wy = iy - y0f;
        int x0 = (int)x0f;
        int y0 = (int)y0f;
        int x1 = min(x0 + 1, WSP - 1);
        int y1 = min(y0 + 1, HSP - 1);

        float v00 = kbase[(size_t)(y0 * WSP + x0) * CC];
        float v01 = kbase[(size_t)(y0 * WSP + x1) * CC];
        float v10 = kbase[(size_t)(y1 * WSP + x0) * CC];
        float v11 = kbase[(size_t)(y1 * WSP + x1) * CC];

        float s = (1.0f - wy) * ((1.0f - wx) * v00 + wx * v01)
                +          wy * ((1.0f - wx) * v10 + wx * v11);
        sv[p] = s;

        float d = qv * s;
        #pragma unroll
        for (int o = 16; o; o >>= 1)
            d += __shfl_down_sync(0xffffffffu, d, o);
        if (lane == 0) red[p][wid] = d;
    }
    __syncthreads();

    if (t < PTS) {
        const float scale = 0.088388347648318447f;
        sc[t] = (red[t][0] + red[t][1] + red[t][2] + red[t][3]) * scale;
    }
    __syncthreads();

    float m = sc[0];
    #pragma unroll
    for (int p = 1; p < PTS; p++) m = fmaxf(m, sc[p]);
    float e[PTS];
    float denom = 0.0f;
    #pragma unroll
    for (int p = 0; p < PTS; p++) { e[p] = expf(sc[p] - m); denom += e[p]; }
    float inv = 1.0f / denom;

    float o = 0.0f;
    #pragma unroll
    for (int p = 0; p < PTS; p++) o += e[p] * inv * sv[p];

    out[(size_t)bn * CC + h * HD + t] = o;
}

// ============================ Launch ============================
extern "C" void kernel_launch(void* const* d_in, const int* in_sizes, int n_in,
                              void* d_out, int out_size)
{
    const float* query = (const float*)d_in[0];
    const float* ref   = (const float*)d_in[1];
    const float* Wq    = (const float*)d_in[2];
    const float* bq    = (const float*)d_in[3];
    const float* Wkv   = (const float*)d_in[4];
    const float* bkv   = (const float*)d_in[5];
    const float* Woff  = (const float*)d_in[6];
    const float* boff  = (const float*)d_in[7];
    const float* Wout  = (const float*)d_in[8];
    const float* bout  = (const float*)d_in[9];
    float* out = (float*)d_out;

    float *q_ptr, *k_ptr, *off_ptr, *attn_ptr;
    cudaGetSymbolAddress((void**)&q_ptr,    g_q);
    cudaGetSymbolAddress((void**)&k_ptr,    g_k);
    cudaGetSymbolAddress((void**)&off_ptr,  g_off);
    cudaGetSymbolAddress((void**)&attn_ptr, g_attn);

    // Which gemm_tc body got loaded? tcgen05 body uses many registers; the
    // plain-arch stub uses almost none. Deterministic across calls.
    cudaFuncAttributes fa;
    cudaFuncGetAttributes(&fa, gemm_tc);
    bool use_tc = (fa.numRegs > 32);

    if (use_tc) {
        __nv_bfloat16 *qh, *ql, *rh, *rl, *ah, *al;
        __nv_bfloat16 *wqh, *wql, *wkh, *wkl, *woh, *wol, *wfh, *wfl;
        cudaGetSymbolAddress((void**)&qh, g_qh);   cudaGetSymbolAddress((void**)&ql, g_ql);
        cudaGetSymbolAddress((void**)&rh, g_rh);   cudaGetSymbolAddress((void**)&rl, g_rl);
        cudaGetSymbolAddress((void**)&ah, g_ah);   cudaGetSymbolAddress((void**)&al, g_al);
        cudaGetSymbolAddress((void**)&wqh, g_WqT_h); cudaGetSymbolAddress((void**)&wql, g_WqT_l);
        cudaGetSymbolAddress((void**)&wkh, g_WkT_h); cudaGetSymbolAddress((void**)&wkl, g_WkT_l);
        cudaGetSymbolAddress((void**)&woh, g_WoT_h); cudaGetSymbolAddress((void**)&wol, g_WoT_l);
        cudaGetSymbolAddress((void**)&wfh, g_WoffT_h); cudaGetSymbolAddress((void**)&wfl, g_WoffT_l);

        cudaFuncSetAttribute(gemm_tc, cudaFuncAttributeMaxDynamicSharedMemorySize, GEMM_SMEM);

        const int nA = BN * CC;
        split_kernel<<<2048, 256>>>(query, qh, ql, nA);
        split_kernel<<<2048, 256>>>(ref,   rh, rl, nA);
        dim3 t32(32, 32);
        tsplit_kernel<<<dim3(32, 32), t32>>>(Wq,   wqh, wql, CC, CC, CC);
        tsplit_kernel<<<dim3(32, 32), t32>>>(Wkv,  wkh, wkl, CC, CC, 2 * CC);
        tsplit_kernel<<<dim3(4,  32), t32>>>(Woff, wfh, wfl, CC, 128, 128);
        tsplit_kernel<<<dim3(32, 32), t32>>>(Wout, woh, wol, CC, CC, CC);

        const int gy = (BN + 127) / 128;   // 86
        gemm_tc<<<dim3(8, gy), 128, GEMM_SMEM>>>(qh, ql, wqh, wql, bq,   q_ptr,   BN, CC);
        gemm_tc<<<dim3(8, gy), 128, GEMM_SMEM>>>(rh, rl, wkh, wkl, bkv,  k_ptr,   BN, CC);
        gemm_tc<<<dim3(1, gy), 128, GEMM_SMEM>>>(qh, ql, wfh, wfl, boff, off_ptr, BN, 128);

        attn_kernel<<<dim3(BN, HEADS), 128>>>(attn_ptr);

        split_kernel<<<2048, 256>>>(attn_ptr, ah, al, nA);
        gemm_tc<<<dim3(8, gy), 128, GEMM_SMEM>>>(ah, al, woh, wol, bout, out, BN, CC);
    } else {
        dim3 blk(256);
        dim3 gBig((CC + 63) / 64, (BN + 63) / 64);
        dim3 gOff((128 + 63) / 64, (BN + 63) / 64);

        sgemm_bias_kernel<<<gBig, blk>>>(query, Wq, bq, q_ptr, BN, CC, CC, CC);
        sgemm_bias_kernel<<<gBig, blk>>>(ref, Wkv, bkv, k_ptr, BN, CC, CC, 2 * CC);
        sgemm_bias_kernel<<<gOff, blk>>>(query, Woff, boff, off_ptr, BN, HEADS * PTS * 2, CC, HEADS * PTS * 2);

        attn_kernel<<<dim3(BN, HEADS), 128>>>(attn_ptr);

        sgemm_bias_kernel<<<gBig, blk>>>(attn_ptr, Wout, bout, out, BN, CC, CC, CC);
    }
}

// round 4
// speedup vs baseline: 6.6079x; 1.8598x over previous
#include <cuda_runtime.h>
#include <cuda_bf16.h>
#include <cstdint>
#include <math.h>

#define NB   8
#define HSP  37
#define WSP  37
#define NPIX 1369
#define BN   10952
#define CC   1024
#define HEADS 8
#define HD   128
#define PTS  8
#define MBLK 86
#define MPAD (MBLK * 128)   // 11008
#define NCH  16             // K chunks of 64
#define TILE_BYTES 16384    // 128 rows x 128B

#if defined(__CUDA_ARCH__) && (defined(__CUDA_ARCH_FEAT_SM103_ALL) || defined(__CUDA_ARCH_FEAT_SM100_ALL) || defined(__CUDA_ARCH_SPECIFIC__))
#define HAS_TCGEN05 1
#else
#define HAS_TCGEN05 0
#endif

#define SMEM_SWIZZLE_128B(byte_offset) ((byte_offset) ^ (((byte_offset) >> 3) & 0x70))

// ============================ Scratch ============================
__device__ float g_q[BN * CC];
__device__ float g_k[BN * CC];
__device__ float g_off[BN * HEADS * PTS * 2];
__device__ float g_attn[BN * CC];

// Blocked+swizzled bf16 hi/lo operands (16KB tiles, tile (r,c) at ((r*NCH)+c)*16KB)
__device__ __nv_bfloat16 g_qh[MPAD * CC];
__device__ __nv_bfloat16 g_ql[MPAD * CC];
__device__ __nv_bfloat16 g_rh[MPAD * CC];
__device__ __nv_bfloat16 g_rl[MPAD * CC];
__device__ __nv_bfloat16 g_ah[MPAD * CC];
__device__ __nv_bfloat16 g_al[MPAD * CC];
__device__ __nv_bfloat16 g_WqT_h[CC * CC];
__device__ __nv_bfloat16 g_WqT_l[CC * CC];
__device__ __nv_bfloat16 g_WkT_h[CC * CC];
__device__ __nv_bfloat16 g_WkT_l[CC * CC];
__device__ __nv_bfloat16 g_WoT_h[CC * CC];
__device__ __nv_bfloat16 g_WoT_l[CC * CC];
__device__ __nv_bfloat16 g_WoffT_h[128 * CC];
__device__ __nv_bfloat16 g_WoffT_l[128 * CC];

// ============================ tcgen05 helpers (guarded) ============================
#if HAS_TCGEN05
__device__ __forceinline__ uint32_t smem_to_u32(const void* p) {
    uint32_t a;
    asm("{ .reg .u64 t; cvta.to.shared.u64 t, %1; cvt.u32.u64 %0, t; }" : "=r"(a) : "l"(p));
    return a;
}
#define TCGEN05_ALLOC(smem_result_addr, nCols) \
    asm volatile("tcgen05.alloc.cta_group::1.sync.aligned.shared::cta.b32 [%0], %1;" \
        :: "r"((uint32_t)(smem_result_addr)), "r"((uint32_t)(nCols)) : "memory")
#define TCGEN05_DEALLOC(tmem_addr, nCols) \
    asm volatile("tcgen05.dealloc.cta_group::1.sync.aligned.b32 %0, %1;" :: "r"(tmem_addr), "r"(nCols))
#define TCGEN05_RELINQUISH_ALLOC_PERMIT() \
    asm volatile("tcgen05.relinquish_alloc_permit.cta_group::1.sync.aligned;")
#define TCGEN05_COMMIT(mbar_smem_addr) \
    asm volatile("tcgen05.commit.cta_group::1.mbarrier::arrive::one.shared::cluster.b64 [%0];" \
        :: "r"((uint32_t)(mbar_smem_addr)) : "memory")
#define TCGEN05_WAIT_LD() asm volatile("tcgen05.wait::ld.sync.aligned;" ::: "memory")
#define TCGEN05_FENCE_AFTER() asm volatile("tcgen05.fence::after_thread_sync;" ::: "memory")
#define TCGEN05_FENCE_BEFORE() asm volatile("tcgen05.fence::before_thread_sync;" ::: "memory")
#define MBARRIER_INIT(mbar_smem_addr, count) \
    asm volatile("mbarrier.init.shared.b64 [%0], %1;" \
        :: "r"((uint32_t)(mbar_smem_addr)), "r"((uint32_t)(count)) : "memory")
#define MBARRIER_EXPECT_TX(mbar_smem_addr, tx_bytes) \
    asm volatile("mbarrier.arrive.expect_tx.shared.b64 _, [%0], %1;" \
        :: "r"((uint32_t)(mbar_smem_addr)), "r"((uint32_t)(tx_bytes)) : "memory")
#define MBARRIER_WAIT_PARITY(mbar_smem_addr, phase_parity) do { \
    uint32_t _mbar = (uint32_t)(mbar_smem_addr); \
    uint32_t _parity = (uint32_t)(phase_parity); \
    uint32_t _done; \
    asm volatile("{\n\t.reg .pred p;\n\t" \
        "mbarrier.try_wait.parity.acquire.cta.shared::cta.b64 p, [%1], %2;\n\t" \
        "selp.b32 %0, 1, 0, p;\n\t}" : "=r"(_done) : "r"(_mbar), "r"(_parity) : "memory"); \
    if (!_done) { \
        asm volatile("{\n\t.reg .pred P1;\n\t" \
            "WAIT_LOOP_%=:\n\t" \
            "mbarrier.try_wait.parity.acquire.cta.shared::cta.b64 P1, [%0], %1, 0x989680;\n\t" \
            "@P1 bra.uni WAIT_DONE_%=;\n\t" \
            "bra.uni WAIT_LOOP_%=;\n\t" \
            "WAIT_DONE_%=:\n\t}" :: "r"(_mbar), "r"(_parity) : "memory"); \
    } \
} while(0)
#define TCGEN05_LD_32X32B_X32(r, tmem_addr) \
    asm volatile("tcgen05.ld.sync.aligned.32x32b.x32.b32 " \
        "{%0, %1, %2, %3, %4, %5, %6, %7, %8, %9, %10, %11, %12, %13, %14, %15, " \
        " %16, %17, %18, %19, %20, %21, %22, %23, %24, %25, %26, %27, %28, %29, %30, %31}, [%32];" \
        : "=r"((r)[0]),  "=r"((r)[1]),  "=r"((r)[2]),  "=r"((r)[3]), \
          "=r"((r)[4]),  "=r"((r)[5]),  "=r"((r)[6]),  "=r"((r)[7]), \
          "=r"((r)[8]),  "=r"((r)[9]),  "=r"((r)[10]), "=r"((r)[11]), \
          "=r"((r)[12]), "=r"((r)[13]), "=r"((r)[14]), "=r"((r)[15]), \
          "=r"((r)[16]), "=r"((r)[17]), "=r"((r)[18]), "=r"((r)[19]), \
          "=r"((r)[20]), "=r"((r)[21]), "=r"((r)[22]), "=r"((r)[23]), \
          "=r"((r)[24]), "=r"((r)[25]), "=r"((r)[26]), "=r"((r)[27]), \
          "=r"((r)[28]), "=r"((r)[29]), "=r"((r)[30]), "=r"((r)[31]) \
        : "r"(tmem_addr))

static constexpr uint64_t SMEM_DESC_BASE_SW128 =
    (uint64_t(2)  << 61) | (uint64_t(1) << 46) | (uint64_t(64) << 32) | (uint64_t(1) << 16);
#define MAKE_SMEM_DESC(base_addr) (SMEM_DESC_BASE_SW128 | ((uint64_t)((base_addr) >> 4) & 0x3FFF))

__device__ __forceinline__ void mma_f16_ss(uint32_t d, uint64_t ad, uint64_t bd,
                                           uint32_t idesc, bool en) {
    uint32_t e = en ? 1u : 0u;
    asm volatile(
        "{\n\t.reg .pred p;\n\tsetp.ne.u32 p, %5, 0;\n\t"
        "tcgen05.mma.cta_group::1.kind::f16 [%0], %1, %2, %3, {%4, %4, %4, %4}, p;\n\t}"
        :: "r"(d), "l"(ad), "l"(bd), "r"(idesc), "r"(0u), "r"(e) : "memory");
}
__device__ __forceinline__ void bulk_g2s(uint32_t dst, const void* src, uint32_t bytes, uint32_t mbar) {
    asm volatile("cp.async.bulk.shared::cluster.global.mbarrier::complete_tx::bytes [%0], [%1], %2, [%3];"
        :: "r"(dst), "l"(src), "r"(bytes), "r"(mbar) : "memory");
}
#endif  // HAS_TCGEN05

// ============================ Pack kernels ============================
// Activations fp32 row-major [M,1024] -> blocked swizzled bf16 hi/lo tiles.
// grid (NCH, MBLK), block 128. thread: unit j = t&7 (16B), rows in groups of 16.
__global__ void split_act_kernel(const float* __restrict__ src,
                                 __nv_bfloat16* __restrict__ hi,
                                 __nv_bfloat16* __restrict__ lo, int M)
{
    const int c  = blockIdx.x;
    const int mb = blockIdx.y;
    const int t  = threadIdx.x;
    const int j  = t & 7;
    char* hbase = (char*)hi + ((size_t)(mb * NCH + c)) * TILE_BYTES;
    char* lbase = (char*)lo + ((size_t)(mb * NCH + c)) * TILE_BYTES;

    #pragma unroll
    for (int g = 0; g < 8; g++) {
        int ml = g * 16 + (t >> 3);
        int m = mb * 128 + ml;
        float x[8];
        if (m < M) {
            float4 a = *(const float4*)(src + (size_t)m * CC + c * 64 + j * 8);
            float4 b = *(const float4*)(src + (size_t)m * CC + c * 64 + j * 8 + 4);
            x[0]=a.x; x[1]=a.y; x[2]=a.z; x[3]=a.w; x[4]=b.x; x[5]=b.y; x[6]=b.z; x[7]=b.w;
        } else {
            #pragma unroll
            for (int i = 0; i < 8; i++) x[i] = 0.0f;
        }
        __nv_bfloat16 h[8], l[8];
        #pragma unroll
        for (int i = 0; i < 8; i++) {
            h[i] = __float2bfloat16(x[i]);
            l[i] = __float2bfloat16(x[i] - __bfloat162float(h[i]));
        }
        uint32_t off = SMEM_SWIZZLE_128B((uint32_t)(ml * 128 + j * 16));
        *(uint4*)(hbase + off) = *(uint4*)h;
        *(uint4*)(lbase + off) = *(uint4*)l;
    }
}

// Weights fp32 [K=1024, ldw] -> transposed blocked swizzled bf16 hi/lo ([N rows, K]).
// grid (NCH, N/128), block 128.
__global__ void pack_weight_kernel(const float* __restrict__ W,
                                   __nv_bfloat16* __restrict__ hi,
                                   __nv_bfloat16* __restrict__ lo, int ldw)
{
    __shared__ float ts[64][129];
    const int c  = blockIdx.x;
    const int nb = blockIdx.y;
    const int t  = threadIdx.x;
    const int k0 = c * 64;
    const int n0 = nb * 128;

    #pragma unroll 4
    for (int i = 0; i < 64; i++)
        ts[i][t] = W[(size_t)(k0 + i) * ldw + n0 + t];
    __syncthreads();

    char* hbase = (char*)hi + ((size_t)(nb * NCH + c)) * TILE_BYTES;
    char* lbase = (char*)lo + ((size_t)(nb * NCH + c)) * TILE_BYTES;
    const int j = t & 7;
    #pragma unroll
    for (int g = 0; g < 8; g++) {
        int nl = g * 16 + (t >> 3);
        __nv_bfloat16 h[8], l[8];
        #pragma unroll
        for (int jj = 0; jj < 8; jj++) {
            float x = ts[j * 8 + jj][nl];
            h[jj] = __float2bfloat16(x);
            l[jj] = __float2bfloat16(x - __bfloat162float(h[jj]));
        }
        uint32_t off = SMEM_SWIZZLE_128B((uint32_t)(nl * 128 + j * 16));
        *(uint4*)(hbase + off) = *(uint4*)h;
        *(uint4*)(lbase + off) = *(uint4*)l;
    }
}

// ============================ tcgen05 GEMM (bulk-async, 2-stage) ============================
// C[M, Ncols] = A @ W + bias via 3-pass bf16 split. Tile 128 x NT.
template <int NT>
__global__ void __launch_bounds__(128, 1)
gemm_tc(const char* __restrict__ Ah, const char* __restrict__ Al,
        const char* __restrict__ Bh, const char* __restrict__ Bl,
        const float* __restrict__ bias, float* __restrict__ C, int M, int Ncols)
{
#if HAS_TCGEN05
    constexpr int NBB = NT / 128;                       // B 128-row blocks per tile
    constexpr uint32_t SB = 2 * TILE_BYTES + 2 * NBB * TILE_BYTES;  // stage bytes
    constexpr uint32_t HDR = 1024;
    constexpr uint32_t IDESC = 0x8000490u | ((NT / 8) << 17);

    extern __shared__ char smem[];
    uint32_t sb = smem_to_u32(smem);
    const int tid = threadIdx.x;
    const int wid = tid >> 5;
    const int lane = tid & 31;
    const int m0 = blockIdx.y * 128;
    const int n0 = blockIdx.x * NT;

    if (wid == 0) TCGEN05_ALLOC(sb + 0, NT);
    if (tid == 0) {
        MBARRIER_INIT(sb + 16, 1);  // full0
        MBARRIER_INIT(sb + 24, 1);  // full1
        MBARRIER_INIT(sb + 32, 1);  // empty0
        MBARRIER_INIT(sb + 40, 1);  // empty1
    }
    __syncthreads();
    uint32_t tmem;
    asm volatile("ld.shared.b32 %0, [%1];" : "=r"(tmem) : "r"(sb));

    if (tid == 0) {
        auto issue = [&](int c) {
            int s = c & 1;
            uint32_t fb = sb + 16 + 8u * s;
            uint32_t st = sb + HDR + (uint32_t)s * SB;
            MBARRIER_EXPECT_TX(fb, SB);
            size_t aoff = ((size_t)blockIdx.y * NCH + c) * TILE_BYTES;
            bulk_g2s(st, Ah + aoff, TILE_BYTES, fb);
            bulk_g2s(st + TILE_BYTES, Al + aoff, TILE_BYTES, fb);
            #pragma unroll
            for (int nb = 0; nb < NBB; nb++) {
                size_t boff = ((size_t)(blockIdx.x * NBB + nb) * NCH + c) * TILE_BYTES;
                bulk_g2s(st + 2 * TILE_BYTES + nb * TILE_BYTES, Bh + boff, TILE_BYTES, fb);
                bulk_g2s(st + (2 + NBB) * TILE_BYTES + nb * TILE_BYTES, Bl + boff, TILE_BYTES, fb);
            }
        };
        issue(0);
        issue(1);
        for (int c = 0; c < NCH; c++) {
            int s = c & 1;
            uint32_t fullb = sb + 16 + 8u * s;
            uint32_t emptyb = sb + 32 + 8u * s;
            MBARRIER_WAIT_PARITY(fullb, (uint32_t)((c >> 1) & 1));
            uint32_t st = sb + HDR + (uint32_t)s * SB;
            uint64_t ah = MAKE_SMEM_DESC(st);
            uint64_t al = MAKE_SMEM_DESC(st + TILE_BYTES);
            uint64_t bh = MAKE_SMEM_DESC(st + 2 * TILE_BYTES);
            uint64_t bl = MAKE_SMEM_DESC(st + (2 + NBB) * TILE_BYTES);
            #pragma unroll
            for (int ks = 0; ks < 4; ks++)
                mma_f16_ss(tmem, ah + ks * 2, bh + ks * 2, IDESC, !(c == 0 && ks == 0));
            #pragma unroll
            for (int ks = 0; ks < 4; ks++)
                mma_f16_ss(tmem, ah + ks * 2, bl + ks * 2, IDESC, true);
            #pragma unroll
            for (int ks = 0; ks < 4; ks++)
                mma_f16_ss(tmem, al + ks * 2, bh + ks * 2, IDESC, true);
            TCGEN05_COMMIT(emptyb);
            if (c + 2 < NCH) {
                MBARRIER_WAIT_PARITY(emptyb, (uint32_t)((c >> 1) & 1));
                issue(c + 2);
            }
        }
        // final: wait last phase (7, parity 1) on both empty barriers
        MBARRIER_WAIT_PARITY(sb + 32, 1u);
        MBARRIER_WAIT_PARITY(sb + 40, 1u);
    }
    __syncthreads();
    TCGEN05_FENCE_AFTER();

    // Epilogue: per-warp transpose through smem (reuse stage region), coalesced STG.
    float* buf = (float*)(smem + HDR) + wid * (32 * 33);
    #pragma unroll
    for (int base = 0; base < NT; base += 32) {
        uint32_t r[32];
        TCGEN05_LD_32X32B_X32(r, tmem + base);
        TCGEN05_WAIT_LD();
        #pragma unroll
        for (int q = 0; q < 32; q++) buf[lane * 33 + q] = __uint_as_float(r[q]);
        __syncwarp();
        float bv = bias[n0 + base + lane];
        #pragma unroll 4
        for (int rr = 0; rr < 32; rr++) {
            int gm = m0 + wid * 32 + rr;
            if (gm < M)
                C[(size_t)gm * Ncols + n0 + base + lane] = buf[rr * 33 + lane] + bv;
        }
        __syncwarp();
    }
    TCGEN05_FENCE_BEFORE();
    __syncthreads();
    if (wid == 0) {
        TCGEN05_RELINQUISH_ALLOC_PERMIT();
        TCGEN05_DEALLOC(tmem, NT);
    }
#endif
}

// ============================ Fallback SGEMM ============================
__global__ void sgemm_bias_kernel(const float* __restrict__ A,
                                  const float* __restrict__ Wt,
                                  const float* __restrict__ bias,
                                  float* __restrict__ C,
                                  int M, int Ncols, int K, int ldw)
{
    __shared__ float As[16][64];
    __shared__ float Bs[16][64];
    const int tid = threadIdx.x;
    const int tx = tid & 15;
    const int ty = tid >> 4;
    const int n0 = blockIdx.x * 64;
    const int m0 = blockIdx.y * 64;
    float acc[4][4] = {};
    for (int k0 = 0; k0 < K; k0 += 16) {
        #pragma unroll
        for (int i = 0; i < 4; i++) {
            int idx = tid + i * 256;
            int m  = idx >> 4, kk = idx & 15, gm = m0 + m;
            As[kk][m] = (gm < M) ? A[(size_t)gm * K + (k0 + kk)] : 0.0f;
        }
        #pragma unroll
        for (int i = 0; i < 4; i++) {
            int idx = tid + i * 256;
            int kk = idx >> 6, n = idx & 63, gn = n0 + n;
            Bs[kk][n] = (gn < Ncols) ? Wt[(size_t)(k0 + kk) * ldw + gn] : 0.0f;
        }
        __syncthreads();
        #pragma unroll
        for (int kk = 0; kk < 16; kk++) {
            float4 a = *(const float4*)&As[kk][ty * 4];
            float4 w = *(const float4*)&Bs[kk][tx * 4];
            acc[0][0] += a.x*w.x; acc[0][1] += a.x*w.y; acc[0][2] += a.x*w.z; acc[0][3] += a.x*w.w;
            acc[1][0] += a.y*w.x; acc[1][1] += a.y*w.y; acc[1][2] += a.y*w.z; acc[1][3] += a.y*w.w;
            acc[2][0] += a.z*w.x; acc[2][1] += a.z*w.y; acc[2][2] += a.z*w.z; acc[2][3] += a.z*w.w;
            acc[3][0] += a.w*w.x; acc[3][1] += a.w*w.y; acc[3][2] += a.w*w.z; acc[3][3] += a.w*w.w;
        }
        __syncthreads();
    }
    #pragma unroll
    for (int r = 0; r < 4; r++) {
        int gm = m0 + ty * 4 + r;
        if (gm >= M) continue;
        #pragma unroll
        for (int c = 0; c < 4; c++) {
            int gn = n0 + tx * 4 + c;
            if (gn < Ncols) C[(size_t)gm * Ncols + gn] = acc[r][c] + bias[gn];
        }
    }
}

// ============================ Attention (warp per (bn,h)) ============================
// Reads g_q/g_k/g_off fp32; writes bf16 hi/lo DIRECTLY into blocked GEMM layout.
__global__ void attn_warp_kernel()
{
    const int bn = blockIdx.x;
    const int h  = threadIdx.x >> 5;
    const int lane = threadIdx.x & 31;

    const int b = bn / NPIX;
    const int n = bn % NPIX;
    const int row = n / WSP;
    const int col = n % WSP;
    const float step = 2.0f / 36.0f;
    const float ybase = -1.0f + row * step;
    const float xbase = -1.0f + col * step;

    float4 q4 = *(const float4*)(g_q + (size_t)bn * CC + h * HD + lane * 4);
    const float* kbase = g_k + (size_t)b * NPIX * CC + h * HD + lane * 4;

    float offv = 0.0f;
    if (lane < 16) offv = g_off[(size_t)bn * (HEADS * PTS * 2) + h * (PTS * 2) + lane];

    float4 sv[PTS];
    float sc[PTS];
    #pragma unroll
    for (int p = 0; p < PTS; p++) {
        float o0 = __shfl_sync(0xffffffffu, offv, 2 * p);
        float o1 = __shfl_sync(0xffffffffu, offv, 2 * p + 1);
        float xn = ybase + o0;
        float yn = xbase + o1;
        float ix = fminf(fmaxf((xn + 1.0f) * 0.5f * (WSP - 1), 0.0f), (float)(WSP - 1));
        float iy = fminf(fmaxf((yn + 1.0f) * 0.5f * (HSP - 1), 0.0f), (float)(HSP - 1));
        float x0f = floorf(ix), y0f = floorf(iy);
        float wx = ix - x0f, wy = iy - y0f;
        int x0 = (int)x0f, y0 = (int)y0f;
        int x1 = min(x0 + 1, WSP - 1);
        int y1 = min(y0 + 1, HSP - 1);

        float4 v00 = *(const float4*)(kbase + (size_t)(y0 * WSP + x0) * CC);
        float4 v01 = *(const float4*)(kbase + (size_t)(y0 * WSP + x1) * CC);
        float4 v10 = *(const float4*)(kbase + (size_t)(y1 * WSP + x0) * CC);
        float4 v11 = *(const float4*)(kbase + (size_t)(y1 * WSP + x1) * CC);

        float w00 = (1.0f - wy) * (1.0f - wx), w01 = (1.0f - wy) * wx;
        float w10 = wy * (1.0f - wx), w11 = wy * wx;
        float4 s;
        s.x = w00*v00.x + w01*v01.x + w10*v10.x + w11*v11.x;
        s.y = w00*v00.y + w01*v01.y + w10*v10.y + w11*v11.y;
        s.z = w00*v00.z + w01*v01.z + w10*v10.z + w11*v11.z;
        s.w = w00*v00.w + w01*v01.w + w10*v10.w + w11*v11.w;
        sv[p] = s;

        float d = q4.x*s.x + q4.y*s.y + q4.z*s.z + q4.w*s.w;
        #pragma unroll
        for (int o = 16; o; o >>= 1) d += __shfl_xor_sync(0xffffffffu, d, o);
        sc[p] = d * 0.088388347648318447f;
    }

    float m = sc[0];
    #pragma unroll
    for (int p = 1; p < PTS; p++) m = fmaxf(m, sc[p]);
    float e[PTS], denom = 0.0f;
    #pragma unroll
    for (int p = 0; p < PTS; p++) { e[p] = expf(sc[p] - m); denom += e[p]; }
    float inv = 1.0f / denom;

    float4 o = make_float4(0, 0, 0, 0);
    #pragma unroll
    for (int p = 0; p < PTS; p++) {
        float w = e[p] * inv;
        o.x += w * sv[p].x; o.y += w * sv[p].y; o.z += w * sv[p].z; o.w += w * sv[p].w;
    }

    // Write bf16 hi/lo into blocked swizzled layout: m=bn, k=h*128+lane*4
    int k = h * HD + lane * 4;
    int mb = bn >> 7, ml = bn & 127;
    int c = k >> 6, kl = k & 63;
    size_t tbase = ((size_t)(mb * NCH + c)) * TILE_BYTES;
    uint32_t off = SMEM_SWIZZLE_128B((uint32_t)(ml * 128 + kl * 2));

    __nv_bfloat16 h4[4], l4[4];
    float ov[4] = {o.x, o.y, o.z, o.w};
    #pragma unroll
    for (int i = 0; i < 4; i++) {
        h4[i] = __float2bfloat16(ov[i]);
        l4[i] = __float2bfloat16(ov[i] - __bfloat162float(h4[i]));
    }
    *(uint2*)((char*)g_ah + tbase + off) = *(uint2*)h4;
    *(uint2*)((char*)g_al + tbase + off) = *(uint2*)l4;
}

// Fallback attention (fp32 output to g_attn)
__global__ void attn_kernel(float* __restrict__ out)
{
    const int bn = blockIdx.x;
    const int h  = blockIdx.y;
    const int t  = threadIdx.x;
    const int lane = t & 31;
    const int wid  = t >> 5;
    const int b = bn / NPIX;
    const int n = bn % NPIX;
    const int row = n / WSP;
    const int col = n % WSP;
    const float step = 2.0f / 36.0f;
    const float ybase = -1.0f + row * step;
    const float xbase = -1.0f + col * step;
    const float qv = g_q[(size_t)bn * CC + h * HD + t];
    const float* kbase = g_k + (size_t)b * NPIX * CC + h * HD + t;
    const float* offp  = g_off + (size_t)bn * (HEADS * PTS * 2) + h * (PTS * 2);
    float sv[PTS];
    __shared__ float red[PTS][4];
    __shared__ float sc[PTS];
    #pragma unroll
    for (int p = 0; p < PTS; p++) {
        float o0 = offp[p * 2 + 0], o1 = offp[p * 2 + 1];
        float xn = ybase + o0, yn = xbase + o1;
        float ix = fminf(fmaxf((xn + 1.0f) * 0.5f * (WSP - 1), 0.0f), (float)(WSP - 1));
        float iy = fminf(fmaxf((yn + 1.0f) * 0.5f * (HSP - 1), 0.0f), (float)(HSP - 1));
        float x0f = floorf(ix), y0f = floorf(iy);
        float wx = ix - x0f, wy = iy - y0f;
        int x0 = (int)x0f, y0 = (int)y0f;
        int x1 = min(x0 + 1, WSP - 1), y1 = min(y0 + 1, HSP - 1);
        float v00 = kbase[(size_t)(y0 * WSP + x0) * CC];
        float v01 = kbase[(size_t)(y0 * WSP + x1) * CC];
        float v10 = kbase[(size_t)(y1 * WSP + x0) * CC];
        float v11 = kbase[(size_t)(y1 * WSP + x1) * CC];
        float s = (1.0f - wy) * ((1.0f - wx) * v00 + wx * v01)
                +          wy * ((1.0f - wx) * v10 + wx * v11);
        sv[p] = s;
        float d = qv * s;
        #pragma unroll
        for (int o = 16; o; o >>= 1) d += __shfl_down_sync(0xffffffffu, d, o);
        if (lane == 0) red[p][wid] = d;
    }
    __syncthreads();
    if (t < PTS) sc[t] = (red[t][0] + red[t][1] + red[t][2] + red[t][3]) * 0.088388347648318447f;
    __syncthreads();
    float m = sc[0];
    #pragma unroll
    for (int p = 1; p < PTS; p++) m = fmaxf(m, sc[p]);
    float e[PTS], denom = 0.0f;
    #pragma unroll
    for (int p = 0; p < PTS; p++) { e[p] = expf(sc[p] - m); denom += e[p]; }
    float inv = 1.0f / denom;
    float o = 0.0f;
    #pragma unroll
    for (int p = 0; p < PTS; p++) o += e[p] * inv * sv[p];
    out[(size_t)bn * CC + h * HD + t] = o;
}

// Fallback split (fp32 -> row-major bf16 hi/lo unused in fallback; keep old flow)
__global__ void split_kernel(const float* __restrict__ src,
                             __nv_bfloat16* __restrict__ hi,
                             __nv_bfloat16* __restrict__ lo, int n)
{
    int i = blockIdx.x * blockDim.x + threadIdx.x;
    int stride = gridDim.x * blockDim.x;
    for (; i < n; i += stride) {
        float x = src[i];
        __nv_bfloat16 h = __float2bfloat16(x);
        hi[i] = h;
        lo[i] = __float2bfloat16(x - __bfloat162float(h));
    }
}

// ============================ Launch ============================
extern "C" void kernel_launch(void* const* d_in, const int* in_sizes, int n_in,
                              void* d_out, int out_size)
{
    const float* query = (const float*)d_in[0];
    const float* ref   = (const float*)d_in[1];
    const float* Wq    = (const float*)d_in[2];
    const float* bq    = (const float*)d_in[3];
    const float* Wkv   = (const float*)d_in[4];
    const float* bkv   = (const float*)d_in[5];
    const float* Woff  = (const float*)d_in[6];
    const float* boff  = (const float*)d_in[7];
    const float* Wout  = (const float*)d_in[8];
    const float* bout  = (const float*)d_in[9];
    float* out = (float*)d_out;

    float *q_ptr, *k_ptr, *off_ptr, *attn_ptr;
    cudaGetSymbolAddress((void**)&q_ptr,    g_q);
    cudaGetSymbolAddress((void**)&k_ptr,    g_k);
    cudaGetSymbolAddress((void**)&off_ptr,  g_off);
    cudaGetSymbolAddress((void**)&attn_ptr, g_attn);

    cudaFuncAttributes fa;
    cudaFuncGetAttributes(&fa, gemm_tc<256>);
    bool use_tc = (fa.numRegs > 32);

    if (use_tc) {
        char *qh, *ql, *rh, *rl, *ah, *al;
        char *wqh, *wql, *wkh, *wkl, *woh, *wol, *wfh, *wfl;
        cudaGetSymbolAddress((void**)&qh, g_qh);   cudaGetSymbolAddress((void**)&ql, g_ql);
        cudaGetSymbolAddress((void**)&rh, g_rh);   cudaGetSymbolAddress((void**)&rl, g_rl);
        cudaGetSymbolAddress((void**)&ah, g_ah);   cudaGetSymbolAddress((void**)&al, g_al);
        cudaGetSymbolAddress((void**)&wqh, g_WqT_h); cudaGetSymbolAddress((void**)&wql, g_WqT_l);
        cudaGetSymbolAddress((void**)&wkh, g_WkT_h); cudaGetSymbolAddress((void**)&wkl, g_WkT_l);
        cudaGetSymbolAddress((void**)&woh, g_WoT_h); cudaGetSymbolAddress((void**)&wol, g_WoT_l);
        cudaGetSymbolAddress((void**)&wfh, g_WoffT_h); cudaGetSymbolAddress((void**)&wfl, g_WoffT_l);

        static bool attr_set = false;
        if (!attr_set) {
            cudaFuncSetAttribute(gemm_tc<256>, cudaFuncAttributeMaxDynamicSharedMemorySize, 197632);
            cudaFuncSetAttribute(gemm_tc<128>, cudaFuncAttributeMaxDynamicSharedMemorySize, 132096);
            attr_set = true;
        }

        __nv_bfloat16* qh_b = (__nv_bfloat16*)qh; __nv_bfloat16* ql_b = (__nv_bfloat16*)ql;
        __nv_bfloat16* rh_b = (__nv_bfloat16*)rh; __nv_bfloat16* rl_b = (__nv_bfloat16*)rl;

        split_act_kernel<<<dim3(NCH, MBLK), 128>>>(query, qh_b, ql_b, BN);
        split_act_kernel<<<dim3(NCH, MBLK), 128>>>(ref,   rh_b, rl_b, BN);
        pack_weight_kernel<<<dim3(NCH, 8), 128>>>(Wq,   (__nv_bfloat16*)wqh, (__nv_bfloat16*)wql, CC);
        pack_weight_kernel<<<dim3(NCH, 8), 128>>>(Wkv,  (__nv_bfloat16*)wkh, (__nv_bfloat16*)wkl, 2 * CC);
        pack_weight_kernel<<<dim3(NCH, 1), 128>>>(Woff, (__nv_bfloat16*)wfh, (__nv_bfloat16*)wfl, 128);
        pack_weight_kernel<<<dim3(NCH, 8), 128>>>(Wout, (__nv_bfloat16*)woh, (__nv_bfloat16*)wol, CC);

        gemm_tc<256><<<dim3(4, MBLK), 128, 197632>>>(qh, ql, wqh, wql, bq,   q_ptr,   BN, CC);
        gemm_tc<256><<<dim3(4, MBLK), 128, 197632>>>(rh, rl, wkh, wkl, bkv,  k_ptr,   BN, CC);
        gemm_tc<128><<<dim3(1, MBLK), 128, 132096>>>(qh, ql, wfh, wfl, boff, off_ptr, BN, 128);

        attn_warp_kernel<<<BN, 256>>>();

        gemm_tc<256><<<dim3(4, MBLK), 128, 197632>>>(ah, al, woh, wol, bout, out, BN, CC);
    } else {
        dim3 blk(256);
        dim3 gBig((CC + 63) / 64, (BN + 63) / 64);
        dim3 gOff((128 + 63) / 64, (BN + 63) / 64);
        sgemm_bias_kernel<<<gBig, blk>>>(query, Wq, bq, q_ptr, BN, CC, CC, CC);
        sgemm_bias_kernel<<<gBig, blk>>>(ref, Wkv, bkv, k_ptr, BN, CC, CC, 2 * CC);
        sgemm_bias_kernel<<<gOff, blk>>>(query, Woff, boff, off_ptr, BN, HEADS * PTS * 2, CC, HEADS * PTS * 2);
        attn_kernel<<<dim3(BN, HEADS), 128>>>(attn_ptr);
        sgemm_bias_kernel<<<gBig, blk>>>(attn_ptr, Wout, bout, out, BN, CC, CC, CC);
    }
}

// round 5
// speedup vs baseline: 7.0086x; 1.0606x over previous
#include <cuda_runtime.h>
#include <cuda_bf16.h>
#include <cstdint>
#include <math.h>

#define NB   8
#define HSP  37
#define WSP  37
#define NPIX 1369
#define BN   10952
#define CC   1024
#define HEADS 8
#define HD   128
#define PTS  8
#define MBLK 86
#define MPAD (MBLK * 128)   // 11008
#define NCH  16             // K chunks of 64
#define TILE_BYTES 16384    // 128 rows x 128B

#if defined(__CUDA_ARCH__) && (defined(__CUDA_ARCH_FEAT_SM103_ALL) || defined(__CUDA_ARCH_FEAT_SM100_ALL) || defined(__CUDA_ARCH_SPECIFIC__))
#define HAS_TCGEN05 1
#else
#define HAS_TCGEN05 0
#endif

#define SMEM_SWIZZLE_128B(byte_offset) ((byte_offset) ^ (((byte_offset) >> 3) & 0x70))

// ============================ Scratch ============================
__device__ float g_q[BN * CC];
__device__ float g_k[BN * CC];
__device__ float g_off[BN * HEADS * PTS * 2];
__device__ float g_attn[BN * CC];

// Blocked+swizzled bf16 hi/lo operands (16KB tiles, tile (r,c) at ((r*NCH)+c)*16KB)
__device__ __nv_bfloat16 g_qh[MPAD * CC];
__device__ __nv_bfloat16 g_ql[MPAD * CC];
__device__ __nv_bfloat16 g_rh[MPAD * CC];
__device__ __nv_bfloat16 g_rl[MPAD * CC];
__device__ __nv_bfloat16 g_ah[MPAD * CC];
__device__ __nv_bfloat16 g_al[MPAD * CC];
__device__ __nv_bfloat16 g_WqT_h[CC * CC];
__device__ __nv_bfloat16 g_WqT_l[CC * CC];
__device__ __nv_bfloat16 g_WkT_h[CC * CC];
__device__ __nv_bfloat16 g_WkT_l[CC * CC];
__device__ __nv_bfloat16 g_WoT_h[CC * CC];
__device__ __nv_bfloat16 g_WoT_l[CC * CC];
__device__ __nv_bfloat16 g_WoffT_h[128 * CC];
__device__ __nv_bfloat16 g_WoffT_l[128 * CC];

// ============================ tcgen05 helpers (guarded) ============================
#if HAS_TCGEN05
__device__ __forceinline__ uint32_t smem_to_u32(const void* p) {
    uint32_t a;
    asm("{ .reg .u64 t; cvta.to.shared.u64 t, %1; cvt.u32.u64 %0, t; }" : "=r"(a) : "l"(p));
    return a;
}
#define TCGEN05_ALLOC(smem_result_addr, nCols) \
    asm volatile("tcgen05.alloc.cta_group::1.sync.aligned.shared::cta.b32 [%0], %1;" \
        :: "r"((uint32_t)(smem_result_addr)), "r"((uint32_t)(nCols)) : "memory")
#define TCGEN05_DEALLOC(tmem_addr, nCols) \
    asm volatile("tcgen05.dealloc.cta_group::1.sync.aligned.b32 %0, %1;" :: "r"(tmem_addr), "r"(nCols))
#define TCGEN05_RELINQUISH_ALLOC_PERMIT() \
    asm volatile("tcgen05.relinquish_alloc_permit.cta_group::1.sync.aligned;")
#define TCGEN05_COMMIT_MC(mbar_smem_addr, mask) \
    asm volatile("tcgen05.commit.cta_group::1.mbarrier::arrive::one.shared::cluster.multicast::cluster.b64 [%0], %1;" \
        :: "r"((uint32_t)(mbar_smem_addr)), "h"((uint16_t)(mask)) : "memory")
#define TCGEN05_WAIT_LD() asm volatile("tcgen05.wait::ld.sync.aligned;" ::: "memory")
#define TCGEN05_FENCE_AFTER() asm volatile("tcgen05.fence::after_thread_sync;" ::: "memory")
#define TCGEN05_FENCE_BEFORE() asm volatile("tcgen05.fence::before_thread_sync;" ::: "memory")
#define MBARRIER_INIT(mbar_smem_addr, count) \
    asm volatile("mbarrier.init.shared.b64 [%0], %1;" \
        :: "r"((uint32_t)(mbar_smem_addr)), "r"((uint32_t)(count)) : "memory")
#define MBARRIER_EXPECT_TX(mbar_smem_addr, tx_bytes) \
    asm volatile("mbarrier.arrive.expect_tx.shared.b64 _, [%0], %1;" \
        :: "r"((uint32_t)(mbar_smem_addr)), "r"((uint32_t)(tx_bytes)) : "memory")
#define MBARRIER_WAIT_PARITY(mbar_smem_addr, phase_parity) do { \
    uint32_t _mbar = (uint32_t)(mbar_smem_addr); \
    uint32_t _parity = (uint32_t)(phase_parity); \
    uint32_t _done; \
    asm volatile("{\n\t.reg .pred p;\n\t" \
        "mbarrier.try_wait.parity.acquire.cta.shared::cta.b64 p, [%1], %2;\n\t" \
        "selp.b32 %0, 1, 0, p;\n\t}" : "=r"(_done) : "r"(_mbar), "r"(_parity) : "memory"); \
    if (!_done) { \
        asm volatile("{\n\t.reg .pred P1;\n\t" \
            "WAIT_LOOP_%=:\n\t" \
            "mbarrier.try_wait.parity.acquire.cta.shared::cta.b64 P1, [%0], %1, 0x989680;\n\t" \
            "@P1 bra.uni WAIT_DONE_%=;\n\t" \
            "bra.uni WAIT_LOOP_%=;\n\t" \
            "WAIT_DONE_%=:\n\t}" :: "r"(_mbar), "r"(_parity) : "memory"); \
    } \
} while(0)
#define CLUSTER_SYNC() do { \
    asm volatile("barrier.cluster.arrive.aligned;" ::: "memory"); \
    asm volatile("barrier.cluster.wait.aligned;" ::: "memory"); \
} while(0)
#define TCGEN05_LD_32X32B_X32(r, tmem_addr) \
    asm volatile("tcgen05.ld.sync.aligned.32x32b.x32.b32 " \
        "{%0, %1, %2, %3, %4, %5, %6, %7, %8, %9, %10, %11, %12, %13, %14, %15, " \
        " %16, %17, %18, %19, %20, %21, %22, %23, %24, %25, %26, %27, %28, %29, %30, %31}, [%32];" \
        : "=r"((r)[0]),  "=r"((r)[1]),  "=r"((r)[2]),  "=r"((r)[3]), \
          "=r"((r)[4]),  "=r"((r)[5]),  "=r"((r)[6]),  "=r"((r)[7]), \
          "=r"((r)[8]),  "=r"((r)[9]),  "=r"((r)[10]), "=r"((r)[11]), \
          "=r"((r)[12]), "=r"((r)[13]), "=r"((r)[14]), "=r"((r)[15]), \
          "=r"((r)[16]), "=r"((r)[17]), "=r"((r)[18]), "=r"((r)[19]), \
          "=r"((r)[20]), "=r"((r)[21]), "=r"((r)[22]), "=r"((r)[23]), \
          "=r"((r)[24]), "=r"((r)[25]), "=r"((r)[26]), "=r"((r)[27]), \
          "=r"((r)[28]), "=r"((r)[29]), "=r"((r)[30]), "=r"((r)[31]) \
        : "r"(tmem_addr))

static constexpr uint64_t SMEM_DESC_BASE_SW128 =
    (uint64_t(2)  << 61) | (uint64_t(1) << 46) | (uint64_t(64) << 32) | (uint64_t(1) << 16);
#define MAKE_SMEM_DESC(base_addr) (SMEM_DESC_BASE_SW128 | ((uint64_t)((base_addr) >> 4) & 0x3FFF))

__device__ __forceinline__ void mma_f16_ss(uint32_t d, uint64_t ad, uint64_t bd,
                                           uint32_t idesc, bool en) {
    uint32_t e = en ? 1u : 0u;
    asm volatile(
        "{\n\t.reg .pred p;\n\tsetp.ne.u32 p, %5, 0;\n\t"
        "tcgen05.mma.cta_group::1.kind::f16 [%0], %1, %2, %3, {%4, %4, %4, %4}, p;\n\t}"
        :: "r"(d), "l"(ad), "l"(bd), "r"(idesc), "r"(0u), "r"(e) : "memory");
}
__device__ __forceinline__ void bulk_g2s(uint32_t dst, const void* src, uint32_t bytes, uint32_t mbar) {
    asm volatile("cp.async.bulk.shared::cluster.global.mbarrier::complete_tx::bytes [%0], [%1], %2, [%3];"
        :: "r"(dst), "l"(src), "r"(bytes), "r"(mbar) : "memory");
}
__device__ __forceinline__ void bulk_g2s_mc(uint32_t dst, const void* src, uint32_t bytes,
                                            uint32_t mbar, uint16_t mask) {
    asm volatile("cp.async.bulk.shared::cluster.global.mbarrier::complete_tx::bytes.multicast::cluster [%0], [%1], %2, [%3], %4;"
        :: "r"(dst), "l"(src), "r"(bytes), "r"(mbar), "h"(mask) : "memory");
}
__device__ __forceinline__ uint32_t cluster_rank() {
    uint32_t r;
    asm("mov.u32 %0, %%cluster_ctarank;" : "=r"(r));
    return r;
}
#endif  // HAS_TCGEN05

// ============================ Pack kernels ============================
// Activations fp32 row-major [M,1024] -> blocked swizzled bf16 hi/lo tiles.
__global__ void split_act_kernel(const float* __restrict__ src,
                                 __nv_bfloat16* __restrict__ hi,
                                 __nv_bfloat16* __restrict__ lo, int M)
{
    const int c  = blockIdx.x;
    const int mb = blockIdx.y;
    const int t  = threadIdx.x;
    const int j  = t & 7;
    char* hbase = (char*)hi + ((size_t)(mb * NCH + c)) * TILE_BYTES;
    char* lbase = (char*)lo + ((size_t)(mb * NCH + c)) * TILE_BYTES;

    #pragma unroll
    for (int g = 0; g < 8; g++) {
        int ml = g * 16 + (t >> 3);
        int m = mb * 128 + ml;
        float x[8];
        if (m < M) {
            float4 a = *(const float4*)(src + (size_t)m * CC + c * 64 + j * 8);
            float4 b = *(const float4*)(src + (size_t)m * CC + c * 64 + j * 8 + 4);
            x[0]=a.x; x[1]=a.y; x[2]=a.z; x[3]=a.w; x[4]=b.x; x[5]=b.y; x[6]=b.z; x[7]=b.w;
        } else {
            #pragma unroll
            for (int i = 0; i < 8; i++) x[i] = 0.0f;
        }
        __nv_bfloat16 h[8], l[8];
        #pragma unroll
        for (int i = 0; i < 8; i++) {
            h[i] = __float2bfloat16(x[i]);
            l[i] = __float2bfloat16(x[i] - __bfloat162float(h[i]));
        }
        uint32_t off = SMEM_SWIZZLE_128B((uint32_t)(ml * 128 + j * 16));
        *(uint4*)(hbase + off) = *(uint4*)h;
        *(uint4*)(lbase + off) = *(uint4*)l;
    }
}

// Weights fp32 [K=1024, ldw] -> transposed blocked swizzled bf16 hi/lo ([N rows, K]).
// grid (NCH, N/128), block 512. 16 independent coalesced loads per thread.
__global__ void __launch_bounds__(512)
pack_weight_kernel(const float* __restrict__ W,
                   __nv_bfloat16* __restrict__ hi,
                   __nv_bfloat16* __restrict__ lo, int ldw)
{
    __shared__ float ts[64][129];
    const int c  = blockIdx.x;
    const int nb = blockIdx.y;
    const int t  = threadIdx.x;
    const int k0 = c * 64;
    const int n0 = nb * 128;

    const int lrow = t >> 7;       // 0..3
    const int lcol = t & 127;
    #pragma unroll
    for (int i = 0; i < 16; i++) {
        int row = i * 4 + lrow;
        ts[row][lcol] = W[(size_t)(k0 + row) * ldw + n0 + lcol];
    }
    __syncthreads();

    char* hbase = (char*)hi + ((size_t)(nb * NCH + c)) * TILE_BYTES;
    char* lbase = (char*)lo + ((size_t)(nb * NCH + c)) * TILE_BYTES;
    #pragma unroll
    for (int it = 0; it < 2; it++) {
        int idx = t + it * 512;          // 0..1023
        int nl = idx >> 3;
        int j  = idx & 7;
        __nv_bfloat16 h[8], l[8];
        #pragma unroll
        for (int jj = 0; jj < 8; jj++) {
            float x = ts[j * 8 + jj][nl];
            h[jj] = __float2bfloat16(x);
            l[jj] = __float2bfloat16(x - __bfloat162float(h[jj]));
        }
        uint32_t off = SMEM_SWIZZLE_128B((uint32_t)(nl * 128 + j * 16));
        *(uint4*)(hbase + off) = *(uint4*)h;
        *(uint4*)(lbase + off) = *(uint4*)l;
    }
}

// ============================ tcgen05 GEMM (bulk-async, 2-stage, cluster-2 B multicast) ====
// C[M, Ncols] = A @ W + bias via 3-pass bf16 split. Tile 128 x NT.
// Cluster (1,2,1): y-adjacent CTAs share B tiles via multicast; each rank issues
// half the B tiles. Empty barriers count=2, released by multicast commits from both ranks.
template <int NT>
__global__ void __launch_bounds__(128, 1) __cluster_dims__(1, 2, 1)
gemm_tc(const char* __restrict__ Ah, const char* __restrict__ Al,
        const char* __restrict__ Bh, const char* __restrict__ Bl,
        const float* __restrict__ bias, float* __restrict__ C, int M, int Ncols)
{
#if HAS_TCGEN05
    constexpr int NBB = NT / 128;
    constexpr uint32_t SB = (2 + 2 * NBB) * TILE_BYTES;   // stage bytes
    constexpr uint32_t HDR = 1024;
    constexpr uint32_t IDESC = 0x8000490u | ((NT / 8) << 17);

    extern __shared__ char smem[];
    uint32_t sb = smem_to_u32(smem);
    const int tid = threadIdx.x;
    const int wid = tid >> 5;
    const int lane = tid & 31;
    const int m0 = blockIdx.y * 128;
    const int n0 = blockIdx.x * NT;
    const uint32_t rank = cluster_rank();

    if (wid == 0) TCGEN05_ALLOC(sb + 0, NT);
    if (tid == 0) {
        MBARRIER_INIT(sb + 16, 1);  // full0
        MBARRIER_INIT(sb + 24, 1);  // full1
        MBARRIER_INIT(sb + 32, 2);  // empty0 (2 arrivals: both ranks' commits)
        MBARRIER_INIT(sb + 40, 2);  // empty1
    }
    __syncthreads();
    // All cluster barriers initialized before any peer multicast can land.
    CLUSTER_SYNC();
    uint32_t tmem;
    asm volatile("ld.shared.b32 %0, [%1];" : "=r"(tmem) : "r"(sb));

    if (tid == 0) {
        auto issue = [&](int c) {
            int s = c & 1;
            uint32_t fb = sb + 16 + 8u * s;
            uint32_t st = sb + HDR + (uint32_t)s * SB;
            MBARRIER_EXPECT_TX(fb, SB);
            size_t aoff = ((size_t)blockIdx.y * NCH + c) * TILE_BYTES;
            bulk_g2s(st, Ah + aoff, TILE_BYTES, fb);
            bulk_g2s(st + TILE_BYTES, Al + aoff, TILE_BYTES, fb);
            #pragma unroll
            for (int nb = 0; nb < NBB; nb++) {
                size_t boff = ((size_t)(blockIdx.x * NBB + nb) * NCH + c) * TILE_BYTES;
                int th = nb * 2 + 0, tl = nb * 2 + 1;
                if ((uint32_t)(th & 1) == rank)
                    bulk_g2s_mc(st + (2 + nb) * TILE_BYTES, Bh + boff, TILE_BYTES, fb, 3);
                if ((uint32_t)(tl & 1) == rank)
                    bulk_g2s_mc(st + (2 + NBB + nb) * TILE_BYTES, Bl + boff, TILE_BYTES, fb, 3);
            }
        };
        issue(0);
        issue(1);
        for (int c = 0; c < NCH; c++) {
            int s = c & 1;
            uint32_t fullb = sb + 16 + 8u * s;
            uint32_t emptyb = sb + 32 + 8u * s;
            MBARRIER_WAIT_PARITY(fullb, (uint32_t)((c >> 1) & 1));
            uint32_t st = sb + HDR + (uint32_t)s * SB;
            uint64_t ah = MAKE_SMEM_DESC(st);
            uint64_t al = MAKE_SMEM_DESC(st + TILE_BYTES);
            uint64_t bh = MAKE_SMEM_DESC(st + 2 * TILE_BYTES);
            uint64_t bl = MAKE_SMEM_DESC(st + (2 + NBB) * TILE_BYTES);
            #pragma unroll
            for (int ks = 0; ks < 4; ks++)
                mma_f16_ss(tmem, ah + ks * 2, bh + ks * 2, IDESC, !(c == 0 && ks == 0));
            #pragma unroll
            for (int ks = 0; ks < 4; ks++)
                mma_f16_ss(tmem, ah + ks * 2, bl + ks * 2, IDESC, true);
            #pragma unroll
            for (int ks = 0; ks < 4; ks++)
                mma_f16_ss(tmem, al + ks * 2, bh + ks * 2, IDESC, true);
            TCGEN05_COMMIT_MC(emptyb, 3);   // arrive on BOTH ranks' empty[s]
            if (c + 2 < NCH) {
                MBARRIER_WAIT_PARITY(emptyb, (uint32_t)((c >> 1) & 1));
                issue(c + 2);
            }
        }
        MBARRIER_WAIT_PARITY(sb + 32, 1u);
        MBARRIER_WAIT_PARITY(sb + 40, 1u);
    }
    __syncthreads();
    TCGEN05_FENCE_AFTER();

    // Epilogue: per-warp transpose through smem, coalesced STG.
    float* buf = (float*)(smem + HDR) + wid * (32 * 33);
    #pragma unroll
    for (int base = 0; base < NT; base += 32) {
        uint32_t r[32];
        TCGEN05_LD_32X32B_X32(r, tmem + base);
        TCGEN05_WAIT_LD();
        #pragma unroll
        for (int q = 0; q < 32; q++) buf[lane * 33 + q] = __uint_as_float(r[q]);
        __syncwarp();
        float bv = bias[n0 + base + lane];
        #pragma unroll 4
        for (int rr = 0; rr < 32; rr++) {
            int gm = m0 + wid * 32 + rr;
            if (gm < M)
                C[(size_t)gm * Ncols + n0 + base + lane] = buf[rr * 33 + lane] + bv;
        }
        __syncwarp();
    }
    TCGEN05_FENCE_BEFORE();
    __syncthreads();
    if (wid == 0) {
        TCGEN05_RELINQUISH_ALLOC_PERMIT();
        TCGEN05_DEALLOC(tmem, NT);
    }
#endif
}

// ============================ Fallback SGEMM ============================
__global__ void sgemm_bias_kernel(const float* __restrict__ A,
                                  const float* __restrict__ Wt,
                                  const float* __restrict__ bias,
                                  float* __restrict__ C,
                                  int M, int Ncols, int K, int ldw)
{
    __shared__ float As[16][64];
    __shared__ float Bs[16][64];
    const int tid = threadIdx.x;
    const int tx = tid & 15;
    const int ty = tid >> 4;
    const int n0 = blockIdx.x * 64;
    const int m0 = blockIdx.y * 64;
    float acc[4][4] = {};
    for (int k0 = 0; k0 < K; k0 += 16) {
        #pragma unroll
        for (int i = 0; i < 4; i++) {
            int idx = tid + i * 256;
            int m  = idx >> 4, kk = idx & 15, gm = m0 + m;
            As[kk][m] = (gm < M) ? A[(size_t)gm * K + (k0 + kk)] : 0.0f;
        }
        #pragma unroll
        for (int i = 0; i < 4; i++) {
            int idx = tid + i * 256;
            int kk = idx >> 6, n = idx & 63, gn = n0 + n;
            Bs[kk][n] = (gn < Ncols) ? Wt[(size_t)(k0 + kk) * ldw + gn] : 0.0f;
        }
        __syncthreads();
        #pragma unroll
        for (int kk = 0; kk < 16; kk++) {
            float4 a = *(const float4*)&As[kk][ty * 4];
            float4 w = *(const float4*)&Bs[kk][tx * 4];
            acc[0][0] += a.x*w.x; acc[0][1] += a.x*w.y; acc[0][2] += a.x*w.z; acc[0][3] += a.x*w.w;
            acc[1][0] += a.y*w.x; acc[1][1] += a.y*w.y; acc[1][2] += a.y*w.z; acc[1][3] += a.y*w.w;
            acc[2][0] += a.z*w.x; acc[2][1] += a.z*w.y; acc[2][2] += a.z*w.z; acc[2][3] += a.z*w.w;
            acc[3][0] += a.w*w.x; acc[3][1] += a.w*w.y; acc[3][2] += a.w*w.z; acc[3][3] += a.w*w.w;
        }
        __syncthreads();
    }
    #pragma unroll
    for (int r = 0; r < 4; r++) {
        int gm = m0 + ty * 4 + r;
        if (gm >= M) continue;
        #pragma unroll
        for (int c = 0; c < 4; c++) {
            int gn = n0 + tx * 4 + c;
            if (gn < Ncols) C[(size_t)gm * Ncols + gn] = acc[r][c] + bias[gn];
        }
    }
}

// ============================ Attention (warp per (bn,h)) ============================
__global__ void attn_warp_kernel()
{
    const int bn = blockIdx.x;
    const int h  = threadIdx.x >> 5;
    const int lane = threadIdx.x & 31;

    const int b = bn / NPIX;
    const int n = bn % NPIX;
    const int row = n / WSP;
    const int col = n % WSP;
    const float step = 2.0f / 36.0f;
    const float ybase = -1.0f + row * step;
    const float xbase = -1.0f + col * step;

    float4 q4 = *(const float4*)(g_q + (size_t)bn * CC + h * HD + lane * 4);
    const float* kbase = g_k + (size_t)b * NPIX * CC + h * HD + lane * 4;

    float offv = 0.0f;
    if (lane < 16) offv = g_off[(size_t)bn * (HEADS * PTS * 2) + h * (PTS * 2) + lane];

    float4 sv[PTS];
    float sc[PTS];
    #pragma unroll
    for (int p = 0; p < PTS; p++) {
        float o0 = __shfl_sync(0xffffffffu, offv, 2 * p);
        float o1 = __shfl_sync(0xffffffffu, offv, 2 * p + 1);
        float xn = ybase + o0;
        float yn = xbase + o1;
        float ix = fminf(fmaxf((xn + 1.0f) * 0.5f * (WSP - 1), 0.0f), (float)(WSP - 1));
        float iy = fminf(fmaxf((yn + 1.0f) * 0.5f * (HSP - 1), 0.0f), (float)(HSP - 1));
        float x0f = floorf(ix), y0f = floorf(iy);
        float wx = ix - x0f, wy = iy - y0f;
        int x0 = (int)x0f, y0 = (int)y0f;
        int x1 = min(x0 + 1, WSP - 1);
        int y1 = min(y0 + 1, HSP - 1);

        float4 v00 = *(const float4*)(kbase + (size_t)(y0 * WSP + x0) * CC);
        float4 v01 = *(const float4*)(kbase + (size_t)(y0 * WSP + x1) * CC);
        float4 v10 = *(const float4*)(kbase + (size_t)(y1 * WSP + x0) * CC);
        float4 v11 = *(const float4*)(kbase + (size_t)(y1 * WSP + x1) * CC);

        float w00 = (1.0f - wy) * (1.0f - wx), w01 = (1.0f - wy) * wx;
        float w10 = wy * (1.0f - wx), w11 = wy * wx;
        float4 s;
        s.x = w00*v00.x + w01*v01.x + w10*v10.x + w11*v11.x;
        s.y = w00*v00.y + w01*v01.y + w10*v10.y + w11*v11.y;
        s.z = w00*v00.z + w01*v01.z + w10*v10.z + w11*v11.z;
        s.w = w00*v00.w + w01*v01.w + w10*v10.w + w11*v11.w;
        sv[p] = s;

        float d = q4.x*s.x + q4.y*s.y + q4.z*s.z + q4.w*s.w;
        #pragma unroll
        for (int o = 16; o; o >>= 1) d += __shfl_xor_sync(0xffffffffu, d, o);
        sc[p] = d * 0.088388347648318447f;
    }

    float m = sc[0];
    #pragma unroll
    for (int p = 1; p < PTS; p++) m = fmaxf(m, sc[p]);
    float e[PTS], denom = 0.0f;
    #pragma unroll
    for (int p = 0; p < PTS; p++) { e[p] = expf(sc[p] - m); denom += e[p]; }
    float inv = 1.0f / denom;

    float4 o = make_float4(0, 0, 0, 0);
    #pragma unroll
    for (int p = 0; p < PTS; p++) {
        float w = e[p] * inv;
        o.x += w * sv[p].x; o.y += w * sv[p].y; o.z += w * sv[p].z; o.w += w * sv[p].w;
    }

    int k = h * HD + lane * 4;
    int mb = bn >> 7, ml = bn & 127;
    int c = k >> 6, kl = k & 63;
    size_t tbase = ((size_t)(mb * NCH + c)) * TILE_BYTES;
    uint32_t off = SMEM_SWIZZLE_128B((uint32_t)(ml * 128 + kl * 2));

    __nv_bfloat16 h4[4], l4[4];
    float ov[4] = {o.x, o.y, o.z, o.w};
    #pragma unroll
    for (int i = 0; i < 4; i++) {
        h4[i] = __float2bfloat16(ov[i]);
        l4[i] = __float2bfloat16(ov[i] - __bfloat162float(h4[i]));
    }
    *(uint2*)((char*)g_ah + tbase + off) = *(uint2*)h4;
    *(uint2*)((char*)g_al + tbase + off) = *(uint2*)l4;
}

// Fallback attention (fp32 output to g_attn)
__global__ void attn_kernel(float* __restrict__ out)
{
    const int bn = blockIdx.x;
    const int h  = blockIdx.y;
    const int t  = threadIdx.x;
    const int lane = t & 31;
    const int wid  = t >> 5;
    const int b = bn / NPIX;
    const int n = bn % NPIX;
    const int row = n / WSP;
    const int col = n % WSP;
    const float step = 2.0f / 36.0f;
    const float ybase = -1.0f + row * step;
    const float xbase = -1.0f + col * step;
    const float qv = g_q[(size_t)bn * CC + h * HD + t];
    const float* kbase = g_k + (size_t)b * NPIX * CC + h * HD + t;
    const float* offp  = g_off + (size_t)bn * (HEADS * PTS * 2) + h * (PTS * 2);
    float sv[PTS];
    __shared__ float red[PTS][4];
    __shared__ float sc[PTS];
    #pragma unroll
    for (int p = 0; p < PTS; p++) {
        float o0 = offp[p * 2 + 0], o1 = offp[p * 2 + 1];
        float xn = ybase + o0, yn = xbase + o1;
        float ix = fminf(fmaxf((xn + 1.0f) * 0.5f * (WSP - 1), 0.0f), (float)(WSP - 1));
        float iy = fminf(fmaxf((yn + 1.0f) * 0.5f * (HSP - 1), 0.0f), (float)(HSP - 1));
        float x0f = floorf(ix), y0f = floorf(iy);
        float wx = ix - x0f, wy = iy - y0f;
        int x0 = (int)x0f, y0 = (int)y0f;
        int x1 = min(x0 + 1, WSP - 1), y1 = min(y0 + 1, HSP - 1);
        float v00 = kbase[(size_t)(y0 * WSP + x0) * CC];
        float v01 = kbase[(size_t)(y0 * WSP + x1) * CC];
        float v10 = kbase[(size_t)(y1 * WSP + x0) * CC];
        float v11 = kbase[(size_t)(y1 * WSP + x1) * CC];
        float s = (1.0f - wy) * ((1.0f - wx) * v00 + wx * v01)
                +          wy * ((1.0f - wx) * v10 + wx * v11);
        sv[p] = s;
        float d = qv * s;
        #pragma unroll
        for (int o = 16; o; o >>= 1) d += __shfl_down_sync(0xffffffffu, d, o);
        if (lane == 0) red[p][wid] = d;
    }
    __syncthreads();
    if (t < PTS) sc[t] = (red[t][0] + red[t][1] + red[t][2] + red[t][3]) * 0.088388347648318447f;
    __syncthreads();
    float m = sc[0];
    #pragma unroll
    for (int p = 1; p < PTS; p++) m = fmaxf(m, sc[p]);
    float e[PTS], denom = 0.0f;
    #pragma unroll
    for (int p = 0; p < PTS; p++) { e[p] = expf(sc[p] - m); denom += e[p]; }
    float inv = 1.0f / denom;
    float o = 0.0f;
    #pragma unroll
    for (int p = 0; p < PTS; p++) o += e[p] * inv * sv[p];
    out[(size_t)bn * CC + h * HD + t] = o;
}

// ============================ Launch ============================
extern "C" void kernel_launch(void* const* d_in, const int* in_sizes, int n_in,
                              void* d_out, int out_size)
{
    const float* query = (const float*)d_in[0];
    const float* ref   = (const float*)d_in[1];
    const float* Wq    = (const float*)d_in[2];
    const float* bq    = (const float*)d_in[3];
    const float* Wkv   = (const float*)d_in[4];
    const float* bkv   = (const float*)d_in[5];
    const float* Woff  = (const float*)d_in[6];
    const float* boff  = (const float*)d_in[7];
    const float* Wout  = (const float*)d_in[8];
    const float* bout  = (const float*)d_in[9];
    float* out = (float*)d_out;

    float *q_ptr, *k_ptr, *off_ptr, *attn_ptr;
    cudaGetSymbolAddress((void**)&q_ptr,    g_q);
    cudaGetSymbolAddress((void**)&k_ptr,    g_k);
    cudaGetSymbolAddress((void**)&off_ptr,  g_off);
    cudaGetSymbolAddress((void**)&attn_ptr, g_attn);

    cudaFuncAttributes fa;
    cudaFuncGetAttributes(&fa, gemm_tc<256>);
    bool use_tc = (fa.numRegs > 32);

    if (use_tc) {
        char *qh, *ql, *rh, *rl, *ah, *al;
        char *wqh, *wql, *wkh, *wkl, *woh, *wol, *wfh, *wfl;
        cudaGetSymbolAddress((void**)&qh, g_qh);   cudaGetSymbolAddress((void**)&ql, g_ql);
        cudaGetSymbolAddress((void**)&rh, g_rh);   cudaGetSymbolAddress((void**)&rl, g_rl);
        cudaGetSymbolAddress((void**)&ah, g_ah);   cudaGetSymbolAddress((void**)&al, g_al);
        cudaGetSymbolAddress((void**)&wqh, g_WqT_h); cudaGetSymbolAddress((void**)&wql, g_WqT_l);
        cudaGetSymbolAddress((void**)&wkh, g_WkT_h); cudaGetSymbolAddress((void**)&wkl, g_WkT_l);
        cudaGetSymbolAddress((void**)&woh, g_WoT_h); cudaGetSymbolAddress((void**)&wol, g_WoT_l);
        cudaGetSymbolAddress((void**)&wfh, g_WoffT_h); cudaGetSymbolAddress((void**)&wfl, g_WoffT_l);

        static bool attr_set = false;
        if (!attr_set) {
            cudaFuncSetAttribute(gemm_tc<256>, cudaFuncAttributeMaxDynamicSharedMemorySize, 197632);
            cudaFuncSetAttribute(gemm_tc<128>, cudaFuncAttributeMaxDynamicSharedMemorySize, 132096);
            attr_set = true;
        }

        split_act_kernel<<<dim3(NCH, MBLK), 128>>>(query, (__nv_bfloat16*)qh, (__nv_bfloat16*)ql, BN);
        split_act_kernel<<<dim3(NCH, MBLK), 128>>>(ref,   (__nv_bfloat16*)rh, (__nv_bfloat16*)rl, BN);
        pack_weight_kernel<<<dim3(NCH, 8), 512>>>(Wq,   (__nv_bfloat16*)wqh, (__nv_bfloat16*)wql, CC);
        pack_weight_kernel<<<dim3(NCH, 8), 512>>>(Wkv,  (__nv_bfloat16*)wkh, (__nv_bfloat16*)wkl, 2 * CC);
        pack_weight_kernel<<<dim3(NCH, 1), 512>>>(Woff, (__nv_bfloat16*)wfh, (__nv_bfloat16*)wfl, 128);
        pack_weight_kernel<<<dim3(NCH, 8), 512>>>(Wout, (__nv_bfloat16*)woh, (__nv_bfloat16*)wol, CC);

        gemm_tc<256><<<dim3(4, MBLK), 128, 197632>>>(qh, ql, wqh, wql, bq,   q_ptr,   BN, CC);
        gemm_tc<256><<<dim3(4, MBLK), 128, 197632>>>(rh, rl, wkh, wkl, bkv,  k_ptr,   BN, CC);
        gemm_tc<128><<<dim3(1, MBLK), 128, 132096>>>(qh, ql, wfh, wfl, boff, off_ptr, BN, 128);

        attn_warp_kernel<<<BN, 256>>>();

        gemm_tc<256><<<dim3(4, MBLK), 128, 197632>>>(ah, al, woh, wol, bout, out, BN, CC);
    } else {
        dim3 blk(256);
        dim3 gBig((CC + 63) / 64, (BN + 63) / 64);
        dim3 gOff((128 + 63) / 64, (BN + 63) / 64);
        sgemm_bias_kernel<<<gBig, blk>>>(query, Wq, bq, q_ptr, BN, CC, CC, CC);
        sgemm_bias_kernel<<<gBig, blk>>>(ref, Wkv, bkv, k_ptr, BN, CC, CC, 2 * CC);
        sgemm_bias_kernel<<<gOff, blk>>>(query, Woff, boff, off_ptr, BN, HEADS * PTS * 2, CC, HEADS * PTS * 2);
        attn_kernel<<<dim3(BN, HEADS), 128>>>(attn_ptr);
        sgemm_bias_kernel<<<gBig, blk>>>(attn_ptr, Wout, bout, out, BN, CC, CC, CC);
    }
}

// round 6
// speedup vs baseline: 7.1901x; 1.0259x over previous
#include <cuda_runtime.h>
#include <cuda_bf16.h>
#include <cuda_fp16.h>
#include <cstdint>
#include <math.h>

#define NB   8
#define HSP  37
#define WSP  37
#define NPIX 1369
#define BN   10952
#define CC   1024
#define HEADS 8
#define HD   128
#define PTS  8
#define MBLK 86
#define MPAD (MBLK * 128)   // 11008
#define NCH  16             // K chunks of 64
#define TILE_BYTES 16384    // 128 rows x 128B

#if defined(__CUDA_ARCH__) && (defined(__CUDA_ARCH_FEAT_SM103_ALL) || defined(__CUDA_ARCH_FEAT_SM100_ALL) || defined(__CUDA_ARCH_SPECIFIC__))
#define HAS_TCGEN05 1
#else
#define HAS_TCGEN05 0
#endif

#define SMEM_SWIZZLE_128B(byte_offset) ((byte_offset) ^ (((byte_offset) >> 3) & 0x70))

// ============================ Scratch ============================
__device__ float g_q[BN * CC];
__device__ float g_k[BN * CC];          // fallback path only
__device__ __half g_kh[BN * CC];        // tc path: k in fp16 for the gather
__device__ float g_off[BN * HEADS * PTS * 2];
__device__ float g_attn[BN * CC];

// Blocked+swizzled bf16 hi/lo operands (16KB tiles, tile (r,c) at ((r*NCH)+c)*16KB)
__device__ __nv_bfloat16 g_qh[MPAD * CC];
__device__ __nv_bfloat16 g_ql[MPAD * CC];
__device__ __nv_bfloat16 g_rh[MPAD * CC];
__device__ __nv_bfloat16 g_rl[MPAD * CC];
__device__ __nv_bfloat16 g_ah[MPAD * CC];
__device__ __nv_bfloat16 g_al[MPAD * CC];
__device__ __nv_bfloat16 g_WqT_h[CC * CC];
__device__ __nv_bfloat16 g_WqT_l[CC * CC];
__device__ __nv_bfloat16 g_WkT_h[CC * CC];
__device__ __nv_bfloat16 g_WkT_l[CC * CC];
__device__ __nv_bfloat16 g_WoT_h[CC * CC];
__device__ __nv_bfloat16 g_WoT_l[CC * CC];
__device__ __nv_bfloat16 g_WoffT_h[128 * CC];
__device__ __nv_bfloat16 g_WoffT_l[128 * CC];

// ============================ tcgen05 helpers (guarded) ============================
#if HAS_TCGEN05
__device__ __forceinline__ uint32_t smem_to_u32(const void* p) {
    uint32_t a;
    asm("{ .reg .u64 t; cvta.to.shared.u64 t, %1; cvt.u32.u64 %0, t; }" : "=r"(a) : "l"(p));
    return a;
}
#define TCGEN05_ALLOC(smem_result_addr, nCols) \
    asm volatile("tcgen05.alloc.cta_group::1.sync.aligned.shared::cta.b32 [%0], %1;" \
        :: "r"((uint32_t)(smem_result_addr)), "r"((uint32_t)(nCols)) : "memory")
#define TCGEN05_DEALLOC(tmem_addr, nCols) \
    asm volatile("tcgen05.dealloc.cta_group::1.sync.aligned.b32 %0, %1;" :: "r"(tmem_addr), "r"(nCols))
#define TCGEN05_RELINQUISH_ALLOC_PERMIT() \
    asm volatile("tcgen05.relinquish_alloc_permit.cta_group::1.sync.aligned;")
#define TCGEN05_COMMIT_MC(mbar_smem_addr, mask) \
    asm volatile("tcgen05.commit.cta_group::1.mbarrier::arrive::one.shared::cluster.multicast::cluster.b64 [%0], %1;" \
        :: "r"((uint32_t)(mbar_smem_addr)), "h"((uint16_t)(mask)) : "memory")
#define TCGEN05_WAIT_LD() asm volatile("tcgen05.wait::ld.sync.aligned;" ::: "memory")
#define TCGEN05_FENCE_AFTER() asm volatile("tcgen05.fence::after_thread_sync;" ::: "memory")
#define TCGEN05_FENCE_BEFORE() asm volatile("tcgen05.fence::before_thread_sync;" ::: "memory")
#define MBARRIER_INIT(mbar_smem_addr, count) \
    asm volatile("mbarrier.init.shared.b64 [%0], %1;" \
        :: "r"((uint32_t)(mbar_smem_addr)), "r"((uint32_t)(count)) : "memory")
#define MBARRIER_EXPECT_TX(mbar_smem_addr, tx_bytes) \
    asm volatile("mbarrier.arrive.expect_tx.shared.b64 _, [%0], %1;" \
        :: "r"((uint32_t)(mbar_smem_addr)), "r"((uint32_t)(tx_bytes)) : "memory")
#define MBARRIER_WAIT_PARITY(mbar_smem_addr, phase_parity) do { \
    uint32_t _mbar = (uint32_t)(mbar_smem_addr); \
    uint32_t _parity = (uint32_t)(phase_parity); \
    uint32_t _done; \
    asm volatile("{\n\t.reg .pred p;\n\t" \
        "mbarrier.try_wait.parity.acquire.cta.shared::cta.b64 p, [%1], %2;\n\t" \
        "selp.b32 %0, 1, 0, p;\n\t}" : "=r"(_done) : "r"(_mbar), "r"(_parity) : "memory"); \
    if (!_done) { \
        asm volatile("{\n\t.reg .pred P1;\n\t" \
            "WAIT_LOOP_%=:\n\t" \
            "mbarrier.try_wait.parity.acquire.cta.shared::cta.b64 P1, [%0], %1, 0x989680;\n\t" \
            "@P1 bra.uni WAIT_DONE_%=;\n\t" \
            "bra.uni WAIT_LOOP_%=;\n\t" \
            "WAIT_DONE_%=:\n\t}" :: "r"(_mbar), "r"(_parity) : "memory"); \
    } \
} while(0)
#define CLUSTER_SYNC() do { \
    asm volatile("barrier.cluster.arrive.aligned;" ::: "memory"); \
    asm volatile("barrier.cluster.wait.aligned;" ::: "memory"); \
} while(0)
#define TCGEN05_LD_32X32B_X32(r, tmem_addr) \
    asm volatile("tcgen05.ld.sync.aligned.32x32b.x32.b32 " \
        "{%0, %1, %2, %3, %4, %5, %6, %7, %8, %9, %10, %11, %12, %13, %14, %15, " \
        " %16, %17, %18, %19, %20, %21, %22, %23, %24, %25, %26, %27, %28, %29, %30, %31}, [%32];" \
        : "=r"((r)[0]),  "=r"((r)[1]),  "=r"((r)[2]),  "=r"((r)[3]), \
          "=r"((r)[4]),  "=r"((r)[5]),  "=r"((r)[6]),  "=r"((r)[7]), \
          "=r"((r)[8]),  "=r"((r)[9]),  "=r"((r)[10]), "=r"((r)[11]), \
          "=r"((r)[12]), "=r"((r)[13]), "=r"((r)[14]), "=r"((r)[15]), \
          "=r"((r)[16]), "=r"((r)[17]), "=r"((r)[18]), "=r"((r)[19]), \
          "=r"((r)[20]), "=r"((r)[21]), "=r"((r)[22]), "=r"((r)[23]), \
          "=r"((r)[24]), "=r"((r)[25]), "=r"((r)[26]), "=r"((r)[27]), \
          "=r"((r)[28]), "=r"((r)[29]), "=r"((r)[30]), "=r"((r)[31]) \
        : "r"(tmem_addr))

static constexpr uint64_t SMEM_DESC_BASE_SW128 =
    (uint64_t(2)  << 61) | (uint64_t(1) << 46) | (uint64_t(64) << 32) | (uint64_t(1) << 16);
#define MAKE_SMEM_DESC(base_addr) (SMEM_DESC_BASE_SW128 | ((uint64_t)((base_addr) >> 4) & 0x3FFF))

__device__ __forceinline__ void mma_f16_ss(uint32_t d, uint64_t ad, uint64_t bd,
                                           uint32_t idesc, bool en) {
    uint32_t e = en ? 1u : 0u;
    asm volatile(
        "{\n\t.reg .pred p;\n\tsetp.ne.u32 p, %5, 0;\n\t"
        "tcgen05.mma.cta_group::1.kind::f16 [%0], %1, %2, %3, {%4, %4, %4, %4}, p;\n\t}"
        :: "r"(d), "l"(ad), "l"(bd), "r"(idesc), "r"(0u), "r"(e) : "memory");
}
__device__ __forceinline__ void bulk_g2s(uint32_t dst, const void* src, uint32_t bytes, uint32_t mbar) {
    asm volatile("cp.async.bulk.shared::cluster.global.mbarrier::complete_tx::bytes [%0], [%1], %2, [%3];"
        :: "r"(dst), "l"(src), "r"(bytes), "r"(mbar) : "memory");
}
__device__ __forceinline__ void bulk_g2s_mc(uint32_t dst, const void* src, uint32_t bytes,
                                            uint32_t mbar, uint16_t mask) {
    asm volatile("cp.async.bulk.shared::cluster.global.mbarrier::complete_tx::bytes.multicast::cluster [%0], [%1], %2, [%3], %4;"
        :: "r"(dst), "l"(src), "r"(bytes), "r"(mbar), "h"(mask) : "memory");
}
__device__ __forceinline__ uint32_t cluster_rank() {
    uint32_t r;
    asm("mov.u32 %0, %%cluster_ctarank;" : "=r"(r));
    return r;
}
#endif  // HAS_TCGEN05

// ============================ Pack kernels ============================
// Activations fp32 row-major [M,1024] -> blocked swizzled bf16 hi/lo tiles.
// grid (NCH, MBLK, 2): z selects (src0->dst0) or (src1->dst1).
__global__ void split_act2_kernel(const float* __restrict__ src0,
                                  __nv_bfloat16* __restrict__ hi0,
                                  __nv_bfloat16* __restrict__ lo0,
                                  const float* __restrict__ src1,
                                  __nv_bfloat16* __restrict__ hi1,
                                  __nv_bfloat16* __restrict__ lo1, int M)
{
    const float* src = blockIdx.z ? src1 : src0;
    __nv_bfloat16* hi = blockIdx.z ? hi1 : hi0;
    __nv_bfloat16* lo = blockIdx.z ? lo1 : lo0;
    const int c  = blockIdx.x;
    const int mb = blockIdx.y;
    const int t  = threadIdx.x;
    const int j  = t & 7;
    char* hbase = (char*)hi + ((size_t)(mb * NCH + c)) * TILE_BYTES;
    char* lbase = (char*)lo + ((size_t)(mb * NCH + c)) * TILE_BYTES;

    #pragma unroll
    for (int g = 0; g < 8; g++) {
        int ml = g * 16 + (t >> 3);
        int m = mb * 128 + ml;
        float x[8];
        if (m < M) {
            float4 a = *(const float4*)(src + (size_t)m * CC + c * 64 + j * 8);
            float4 b = *(const float4*)(src + (size_t)m * CC + c * 64 + j * 8 + 4);
            x[0]=a.x; x[1]=a.y; x[2]=a.z; x[3]=a.w; x[4]=b.x; x[5]=b.y; x[6]=b.z; x[7]=b.w;
        } else {
            #pragma unroll
            for (int i = 0; i < 8; i++) x[i] = 0.0f;
        }
        __nv_bfloat16 h[8], l[8];
        #pragma unroll
        for (int i = 0; i < 8; i++) {
            h[i] = __float2bfloat16(x[i]);
            l[i] = __float2bfloat16(x[i] - __bfloat162float(h[i]));
        }
        uint32_t off = SMEM_SWIZZLE_128B((uint32_t)(ml * 128 + j * 16));
        *(uint4*)(hbase + off) = *(uint4*)h;
        *(uint4*)(lbase + off) = *(uint4*)l;
    }
}

// All 4 weights in one launch: grid (NCH, 25), block 512.
// y: [0,8) Wq, [8,16) Wkv, 16 Woff, [17,25) Wout.
__global__ void __launch_bounds__(512)
pack_weights_all(const float* __restrict__ Wq, const float* __restrict__ Wkv,
                 const float* __restrict__ Woff, const float* __restrict__ Wout,
                 __nv_bfloat16* __restrict__ wqh, __nv_bfloat16* __restrict__ wql,
                 __nv_bfloat16* __restrict__ wkh, __nv_bfloat16* __restrict__ wkl,
                 __nv_bfloat16* __restrict__ wfh, __nv_bfloat16* __restrict__ wfl,
                 __nv_bfloat16* __restrict__ woh, __nv_bfloat16* __restrict__ wol)
{
    __shared__ float ts[64][129];
    const int c = blockIdx.x;
    const int y = blockIdx.y;
    const int t = threadIdx.x;

    const float* W; int ldw, nb; __nv_bfloat16 *hi, *lo;
    if (y < 8)       { W = Wq;   ldw = CC;     nb = y;      hi = wqh; lo = wql; }
    else if (y < 16) { W = Wkv;  ldw = 2 * CC; nb = y - 8;  hi = wkh; lo = wkl; }
    else if (y < 17) { W = Woff; ldw = 128;    nb = 0;      hi = wfh; lo = wfl; }
    else             { W = Wout; ldw = CC;     nb = y - 17; hi = woh; lo = wol; }

    const int k0 = c * 64;
    const int n0 = nb * 128;
    const int lrow = t >> 7;
    const int lcol = t & 127;
    #pragma unroll
    for (int i = 0; i < 16; i++) {
        int row = i * 4 + lrow;
        ts[row][lcol] = W[(size_t)(k0 + row) * ldw + n0 + lcol];
    }
    __syncthreads();

    char* hbase = (char*)hi + ((size_t)(nb * NCH + c)) * TILE_BYTES;
    char* lbase = (char*)lo + ((size_t)(nb * NCH + c)) * TILE_BYTES;
    #pragma unroll
    for (int it = 0; it < 2; it++) {
        int idx = t + it * 512;
        int nl = idx >> 3;
        int j  = idx & 7;
        __nv_bfloat16 h[8], l[8];
        #pragma unroll
        for (int jj = 0; jj < 8; jj++) {
            float x = ts[j * 8 + jj][nl];
            h[jj] = __float2bfloat16(x);
            l[jj] = __float2bfloat16(x - __bfloat162float(h[jj]));
        }
        uint32_t off = SMEM_SWIZZLE_128B((uint32_t)(nl * 128 + j * 16));
        *(uint4*)(hbase + off) = *(uint4*)h;
        *(uint4*)(lbase + off) = *(uint4*)l;
    }
}

// ============================ tcgen05 GEMM (bulk-async, 2-stage, cluster-2 B multicast) ====
template <int NT, typename TOut>
__global__ void __launch_bounds__(128, 1) __cluster_dims__(1, 2, 1)
gemm_tc(const char* __restrict__ Ah, const char* __restrict__ Al,
        const char* __restrict__ Bh, const char* __restrict__ Bl,
        const float* __restrict__ bias, TOut* __restrict__ C, int M, int Ncols)
{
#if HAS_TCGEN05
    constexpr int NBB = NT / 128;
    constexpr uint32_t SB = (2 + 2 * NBB) * TILE_BYTES;
    constexpr uint32_t HDR = 1024;
    constexpr uint32_t IDESC = 0x8000490u | ((NT / 8) << 17);

    extern __shared__ char smem[];
    uint32_t sb = smem_to_u32(smem);
    const int tid = threadIdx.x;
    const int wid = tid >> 5;
    const int lane = tid & 31;
    const int m0 = blockIdx.y * 128;
    const int n0 = blockIdx.x * NT;
    const uint32_t rank = cluster_rank();

    if (wid == 0) TCGEN05_ALLOC(sb + 0, NT);
    if (tid == 0) {
        MBARRIER_INIT(sb + 16, 1);  // full0
        MBARRIER_INIT(sb + 24, 1);  // full1
        MBARRIER_INIT(sb + 32, 2);  // empty0 (both ranks' commits)
        MBARRIER_INIT(sb + 40, 2);  // empty1
    }
    __syncthreads();
    CLUSTER_SYNC();
    uint32_t tmem;
    asm volatile("ld.shared.b32 %0, [%1];" : "=r"(tmem) : "r"(sb));

    if (tid == 0) {
        auto issue = [&](int c) {
            int s = c & 1;
            uint32_t fb = sb + 16 + 8u * s;
            uint32_t st = sb + HDR + (uint32_t)s * SB;
            MBARRIER_EXPECT_TX(fb, SB);
            size_t aoff = ((size_t)blockIdx.y * NCH + c) * TILE_BYTES;
            bulk_g2s(st, Ah + aoff, TILE_BYTES, fb);
            bulk_g2s(st + TILE_BYTES, Al + aoff, TILE_BYTES, fb);
            #pragma unroll
            for (int nb = 0; nb < NBB; nb++) {
                size_t boff = ((size_t)(blockIdx.x * NBB + nb) * NCH + c) * TILE_BYTES;
                int th = nb * 2 + 0, tl = nb * 2 + 1;
                if ((uint32_t)(th & 1) == rank)
                    bulk_g2s_mc(st + (2 + nb) * TILE_BYTES, Bh + boff, TILE_BYTES, fb, 3);
                if ((uint32_t)(tl & 1) == rank)
                    bulk_g2s_mc(st + (2 + NBB + nb) * TILE_BYTES, Bl + boff, TILE_BYTES, fb, 3);
            }
        };
        issue(0);
        issue(1);
        for (int c = 0; c < NCH; c++) {
            int s = c & 1;
            uint32_t fullb = sb + 16 + 8u * s;
            uint32_t emptyb = sb + 32 + 8u * s;
            MBARRIER_WAIT_PARITY(fullb, (uint32_t)((c >> 1) & 1));
            uint32_t st = sb + HDR + (uint32_t)s * SB;
            uint64_t ah = MAKE_SMEM_DESC(st);
            uint64_t al = MAKE_SMEM_DESC(st + TILE_BYTES);
            uint64_t bh = MAKE_SMEM_DESC(st + 2 * TILE_BYTES);
            uint64_t bl = MAKE_SMEM_DESC(st + (2 + NBB) * TILE_BYTES);
            #pragma unroll
            for (int ks = 0; ks < 4; ks++)
                mma_f16_ss(tmem, ah + ks * 2, bh + ks * 2, IDESC, !(c == 0 && ks == 0));
            #pragma unroll
            for (int ks = 0; ks < 4; ks++)
                mma_f16_ss(tmem, ah + ks * 2, bl + ks * 2, IDESC, true);
            #pragma unroll
            for (int ks = 0; ks < 4; ks++)
                mma_f16_ss(tmem, al + ks * 2, bh + ks * 2, IDESC, true);
            TCGEN05_COMMIT_MC(emptyb, 3);
            if (c + 2 < NCH) {
                MBARRIER_WAIT_PARITY(emptyb, (uint32_t)((c >> 1) & 1));
                issue(c + 2);
            }
        }
        MBARRIER_WAIT_PARITY(sb + 32, 1u);
        MBARRIER_WAIT_PARITY(sb + 40, 1u);
    }
    __syncthreads();
    TCGEN05_FENCE_AFTER();

    // Epilogue: per-warp transpose through smem, coalesced STG.
    float* buf = (float*)(smem + HDR) + wid * (32 * 33);
    #pragma unroll
    for (int base = 0; base < NT; base += 32) {
        uint32_t r[32];
        TCGEN05_LD_32X32B_X32(r, tmem + base);
        TCGEN05_WAIT_LD();
        #pragma unroll
        for (int q = 0; q < 32; q++) buf[lane * 33 + q] = __uint_as_float(r[q]);
        __syncwarp();
        float bv = bias[n0 + base + lane];
        #pragma unroll 4
        for (int rr = 0; rr < 32; rr++) {
            int gm = m0 + wid * 32 + rr;
            if (gm < M)
                C[(size_t)gm * Ncols + n0 + base + lane] = (TOut)(buf[rr * 33 + lane] + bv);
        }
        __syncwarp();
    }
    TCGEN05_FENCE_BEFORE();
    __syncthreads();
    if (wid == 0) {
        TCGEN05_RELINQUISH_ALLOC_PERMIT();
        TCGEN05_DEALLOC(tmem, NT);
    }
#endif
}

// ============================ Fallback SGEMM ============================
__global__ void sgemm_bias_kernel(const float* __restrict__ A,
                                  const float* __restrict__ Wt,
                                  const float* __restrict__ bias,
                                  float* __restrict__ C,
                                  int M, int Ncols, int K, int ldw)
{
    __shared__ float As[16][64];
    __shared__ float Bs[16][64];
    const int tid = threadIdx.x;
    const int tx = tid & 15;
    const int ty = tid >> 4;
    const int n0 = blockIdx.x * 64;
    const int m0 = blockIdx.y * 64;
    float acc[4][4] = {};
    for (int k0 = 0; k0 < K; k0 += 16) {
        #pragma unroll
        for (int i = 0; i < 4; i++) {
            int idx = tid + i * 256;
            int m  = idx >> 4, kk = idx & 15, gm = m0 + m;
            As[kk][m] = (gm < M) ? A[(size_t)gm * K + (k0 + kk)] : 0.0f;
        }
        #pragma unroll
        for (int i = 0; i < 4; i++) {
            int idx = tid + i * 256;
            int kk = idx >> 6, n = idx & 63, gn = n0 + n;
            Bs[kk][n] = (gn < Ncols) ? Wt[(size_t)(k0 + kk) * ldw + gn] : 0.0f;
        }
        __syncthreads();
        #pragma unroll
        for (int kk = 0; kk < 16; kk++) {
            float4 a = *(const float4*)&As[kk][ty * 4];
            float4 w = *(const float4*)&Bs[kk][tx * 4];
            acc[0][0] += a.x*w.x; acc[0][1] += a.x*w.y; acc[0][2] += a.x*w.z; acc[0][3] += a.x*w.w;
            acc[1][0] += a.y*w.x; acc[1][1] += a.y*w.y; acc[1][2] += a.y*w.z; acc[1][3] += a.y*w.w;
            acc[2][0] += a.z*w.x; acc[2][1] += a.z*w.y; acc[2][2] += a.z*w.z; acc[2][3] += a.z*w.w;
            acc[3][0] += a.w*w.x; acc[3][1] += a.w*w.y; acc[3][2] += a.w*w.z; acc[3][3] += a.w*w.w;
        }
        __syncthreads();
    }
    #pragma unroll
    for (int r = 0; r < 4; r++) {
        int gm = m0 + ty * 4 + r;
        if (gm >= M) continue;
        #pragma unroll
        for (int c = 0; c < 4; c++) {
            int gn = n0 + tx * 4 + c;
            if (gn < Ncols) C[(size_t)gm * Ncols + gn] = acc[r][c] + bias[gn];
        }
    }
}

// ============================ Attention (warp per (bn,h)), fp16 k gathers ============
__global__ void attn_warp_kernel()
{
    const int bn = blockIdx.x;
    const int h  = threadIdx.x >> 5;
    const int lane = threadIdx.x & 31;

    const int b = bn / NPIX;
    const int n = bn % NPIX;
    const int row = n / WSP;
    const int col = n % WSP;
    const float step = 2.0f / 36.0f;
    const float ybase = -1.0f + row * step;
    const float xbase = -1.0f + col * step;

    float4 q4 = *(const float4*)(g_q + (size_t)bn * CC + h * HD + lane * 4);
    const __half* kbase = g_kh + (size_t)b * NPIX * CC + h * HD + lane * 4;

    float offv = 0.0f;
    if (lane < 16) offv = g_off[(size_t)bn * (HEADS * PTS * 2) + h * (PTS * 2) + lane];

    float4 sv[PTS];
    float sc[PTS];
    #pragma unroll
    for (int p = 0; p < PTS; p++) {
        float o0 = __shfl_sync(0xffffffffu, offv, 2 * p);
        float o1 = __shfl_sync(0xffffffffu, offv, 2 * p + 1);
        float xn = ybase + o0;
        float yn = xbase + o1;
        float ix = fminf(fmaxf((xn + 1.0f) * 0.5f * (WSP - 1), 0.0f), (float)(WSP - 1));
        float iy = fminf(fmaxf((yn + 1.0f) * 0.5f * (HSP - 1), 0.0f), (float)(HSP - 1));
        float x0f = floorf(ix), y0f = floorf(iy);
        float wx = ix - x0f, wy = iy - y0f;
        int x0 = (int)x0f, y0 = (int)y0f;
        int x1 = min(x0 + 1, WSP - 1);
        int y1 = min(y0 + 1, HSP - 1);

        // 4 fp16x4 gathers (8B per lane, 256B per warp per corner)
        uint2 u00 = *(const uint2*)(kbase + (size_t)(y0 * WSP + x0) * CC);
        uint2 u01 = *(const uint2*)(kbase + (size_t)(y0 * WSP + x1) * CC);
        uint2 u10 = *(const uint2*)(kbase + (size_t)(y1 * WSP + x0) * CC);
        uint2 u11 = *(const uint2*)(kbase + (size_t)(y1 * WSP + x1) * CC);
        float2 a00 = __half22float2(*(__half2*)&u00.x), b00 = __half22float2(*(__half2*)&u00.y);
        float2 a01 = __half22float2(*(__half2*)&u01.x), b01 = __half22float2(*(__half2*)&u01.y);
        float2 a10 = __half22float2(*(__half2*)&u10.x), b10 = __half22float2(*(__half2*)&u10.y);
        float2 a11 = __half22float2(*(__half2*)&u11.x), b11 = __half22float2(*(__half2*)&u11.y);

        float w00 = (1.0f - wy) * (1.0f - wx), w01 = (1.0f - wy) * wx;
        float w10 = wy * (1.0f - wx), w11 = wy * wx;
        float4 s;
        s.x = w00*a00.x + w01*a01.x + w10*a10.x + w11*a11.x;
        s.y = w00*a00.y + w01*a01.y + w10*a10.y + w11*a11.y;
        s.z = w00*b00.x + w01*b01.x + w10*b10.x + w11*b11.x;
        s.w = w00*b00.y + w01*b01.y + w10*b10.y + w11*b11.y;
        sv[p] = s;

        float d = q4.x*s.x + q4.y*s.y + q4.z*s.z + q4.w*s.w;
        #pragma unroll
        for (int o = 16; o; o >>= 1) d += __shfl_xor_sync(0xffffffffu, d, o);
        sc[p] = d * 0.088388347648318447f;
    }

    float m = sc[0];
    #pragma unroll
    for (int p = 1; p < PTS; p++) m = fmaxf(m, sc[p]);
    float e[PTS], denom = 0.0f;
    #pragma unroll
    for (int p = 0; p < PTS; p++) { e[p] = expf(sc[p] - m); denom += e[p]; }
    float inv = 1.0f / denom;

    float4 o = make_float4(0, 0, 0, 0);
    #pragma unroll
    for (int p = 0; p < PTS; p++) {
        float w = e[p] * inv;
        o.x += w * sv[p].x; o.y += w * sv[p].y; o.z += w * sv[p].z; o.w += w * sv[p].w;
    }

    int k = h * HD + lane * 4;
    int mb = bn >> 7, ml = bn & 127;
    int c = k >> 6, kl = k & 63;
    size_t tbase = ((size_t)(mb * NCH + c)) * TILE_BYTES;
    uint32_t off = SMEM_SWIZZLE_128B((uint32_t)(ml * 128 + kl * 2));

    __nv_bfloat16 h4[4], l4[4];
    float ov[4] = {o.x, o.y, o.z, o.w};
    #pragma unroll
    for (int i = 0; i < 4; i++) {
        h4[i] = __float2bfloat16(ov[i]);
        l4[i] = __float2bfloat16(ov[i] - __bfloat162float(h4[i]));
    }
    *(uint2*)((char*)g_ah + tbase + off) = *(uint2*)h4;
    *(uint2*)((char*)g_al + tbase + off) = *(uint2*)l4;
}

// Fallback attention (fp32 k, fp32 output to g_attn)
__global__ void attn_kernel(float* __restrict__ out)
{
    const int bn = blockIdx.x;
    const int h  = blockIdx.y;
    const int t  = threadIdx.x;
    const int lane = t & 31;
    const int wid  = t >> 5;
    const int b = bn / NPIX;
    const int n = bn % NPIX;
    const int row = n / WSP;
    const int col = n % WSP;
    const float step = 2.0f / 36.0f;
    const float ybase = -1.0f + row * step;
    const float xbase = -1.0f + col * step;
    const float qv = g_q[(size_t)bn * CC + h * HD + t];
    const float* kbase = g_k + (size_t)b * NPIX * CC + h * HD + t;
    const float* offp  = g_off + (size_t)bn * (HEADS * PTS * 2) + h * (PTS * 2);
    float sv[PTS];
    __shared__ float red[PTS][4];
    __shared__ float sc[PTS];
    #pragma unroll
    for (int p = 0; p < PTS; p++) {
        float o0 = offp[p * 2 + 0], o1 = offp[p * 2 + 1];
        float xn = ybase + o0, yn = xbase + o1;
        float ix = fminf(fmaxf((xn + 1.0f) * 0.5f * (WSP - 1), 0.0f), (float)(WSP - 1));
        float iy = fminf(fmaxf((yn + 1.0f) * 0.5f * (HSP - 1), 0.0f), (float)(HSP - 1));
        float x0f = floorf(ix), y0f = floorf(iy);
        float wx = ix - x0f, wy = iy - y0f;
        int x0 = (int)x0f, y0 = (int)y0f;
        int x1 = min(x0 + 1, WSP - 1), y1 = min(y0 + 1, HSP - 1);
        float v00 = kbase[(size_t)(y0 * WSP + x0) * CC];
        float v01 = kbase[(size_t)(y0 * WSP + x1) * CC];
        float v10 = kbase[(size_t)(y1 * WSP + x0) * CC];
        float v11 = kbase[(size_t)(y1 * WSP + x1) * CC];
        float s = (1.0f - wy) * ((1.0f - wx) * v00 + wx * v01)
                +          wy * ((1.0f - wx) * v10 + wx * v11);
        sv[p] = s;
        float d = qv * s;
        #pragma unroll
        for (int o = 16; o; o >>= 1) d += __shfl_down_sync(0xffffffffu, d, o);
        if (lane == 0) red[p][wid] = d;
    }
    __syncthreads();
    if (t < PTS) sc[t] = (red[t][0] + red[t][1] + red[t][2] + red[t][3]) * 0.088388347648318447f;
    __syncthreads();
    float m = sc[0];
    #pragma unroll
    for (int p = 1; p < PTS; p++) m = fmaxf(m, sc[p]);
    float e[PTS], denom = 0.0f;
    #pragma unroll
    for (int p = 0; p < PTS; p++) { e[p] = expf(sc[p] - m); denom += e[p]; }
    float inv = 1.0f / denom;
    float o = 0.0f;
    #pragma unroll
    for (int p = 0; p < PTS; p++) o += e[p] * inv * sv[p];
    out[(size_t)bn * CC + h * HD + t] = o;
}

// ============================ Launch ============================
extern "C" void kernel_launch(void* const* d_in, const int* in_sizes, int n_in,
                              void* d_out, int out_size)
{
    const float* query = (const float*)d_in[0];
    const float* ref   = (const float*)d_in[1];
    const float* Wq    = (const float*)d_in[2];
    const float* bq    = (const float*)d_in[3];
    const float* Wkv   = (const float*)d_in[4];
    const float* bkv   = (const float*)d_in[5];
    const float* Woff  = (const float*)d_in[6];
    const float* boff  = (const float*)d_in[7];
    const float* Wout  = (const float*)d_in[8];
    const float* bout  = (const float*)d_in[9];
    float* out = (float*)d_out;

    float *q_ptr, *k_ptr, *off_ptr, *attn_ptr;
    __half* kh_ptr;
    cudaGetSymbolAddress((void**)&q_ptr,    g_q);
    cudaGetSymbolAddress((void**)&k_ptr,    g_k);
    cudaGetSymbolAddress((void**)&kh_ptr,   g_kh);
    cudaGetSymbolAddress((void**)&off_ptr,  g_off);
    cudaGetSymbolAddress((void**)&attn_ptr, g_attn);

    cudaFuncAttributes fa;
    cudaFuncGetAttributes(&fa, gemm_tc<256, float>);
    bool use_tc = (fa.numRegs > 32);

    if (use_tc) {
        char *qh, *ql, *rh, *rl, *ah, *al;
        char *wqh, *wql, *wkh, *wkl, *woh, *wol, *wfh, *wfl;
        cudaGetSymbolAddress((void**)&qh, g_qh);   cudaGetSymbolAddress((void**)&ql, g_ql);
        cudaGetSymbolAddress((void**)&rh, g_rh);   cudaGetSymbolAddress((void**)&rl, g_rl);
        cudaGetSymbolAddress((void**)&ah, g_ah);   cudaGetSymbolAddress((void**)&al, g_al);
        cudaGetSymbolAddress((void**)&wqh, g_WqT_h); cudaGetSymbolAddress((void**)&wql, g_WqT_l);
        cudaGetSymbolAddress((void**)&wkh, g_WkT_h); cudaGetSymbolAddress((void**)&wkl, g_WkT_l);
        cudaGetSymbolAddress((void**)&woh, g_WoT_h); cudaGetSymbolAddress((void**)&wol, g_WoT_l);
        cudaGetSymbolAddress((void**)&wfh, g_WoffT_h); cudaGetSymbolAddress((void**)&wfl, g_WoffT_l);

        static bool attr_set = false;
        if (!attr_set) {
            cudaFuncSetAttribute(gemm_tc<256, float>,  cudaFuncAttributeMaxDynamicSharedMemorySize, 197632);
            cudaFuncSetAttribute(gemm_tc<256, __half>, cudaFuncAttributeMaxDynamicSharedMemorySize, 197632);
            cudaFuncSetAttribute(gemm_tc<128, float>,  cudaFuncAttributeMaxDynamicSharedMemorySize, 132096);
            attr_set = true;
        }

        split_act2_kernel<<<dim3(NCH, MBLK, 2), 128>>>(
            query, (__nv_bfloat16*)qh, (__nv_bfloat16*)ql,
            ref,   (__nv_bfloat16*)rh, (__nv_bfloat16*)rl, BN);
        pack_weights_all<<<dim3(NCH, 25), 512>>>(
            Wq, Wkv, Woff, Wout,
            (__nv_bfloat16*)wqh, (__nv_bfloat16*)wql,
            (__nv_bfloat16*)wkh, (__nv_bfloat16*)wkl,
            (__nv_bfloat16*)wfh, (__nv_bfloat16*)wfl,
            (__nv_bfloat16*)woh, (__nv_bfloat16*)wol);

        gemm_tc<256, float ><<<dim3(4, MBLK), 128, 197632>>>(qh, ql, wqh, wql, bq,   q_ptr,   BN, CC);
        gemm_tc<256, __half><<<dim3(4, MBLK), 128, 197632>>>(rh, rl, wkh, wkl, bkv,  kh_ptr,  BN, CC);
        gemm_tc<128, float ><<<dim3(1, MBLK), 128, 132096>>>(qh, ql, wfh, wfl, boff, off_ptr, BN, 128);

        attn_warp_kernel<<<BN, 256>>>();

        gemm_tc<256, float><<<dim3(4, MBLK), 128, 197632>>>(ah, al, woh, wol, bout, out, BN, CC);
    } else {
        dim3 blk(256);
        dim3 gBig((CC + 63) / 64, (BN + 63) / 64);
        dim3 gOff((128 + 63) / 64, (BN + 63) / 64);
        sgemm_bias_kernel<<<gBig, blk>>>(query, Wq, bq, q_ptr, BN, CC, CC, CC);
        sgemm_bias_kernel<<<gBig, blk>>>(ref, Wkv, bkv, k_ptr, BN, CC, CC, 2 * CC);
        sgemm_bias_kernel<<<gOff, blk>>>(query, Woff, boff, off_ptr, BN, HEADS * PTS * 2, CC, HEADS * PTS * 2);
        attn_kernel<<<dim3(BN, HEADS), 128>>>(attn_ptr);
        sgemm_bias_kernel<<<gBig, blk>>>(attn_ptr, Wout, bout, out, BN, CC, CC, CC);
    }
}

// round 7
// speedup vs baseline: 8.0671x; 1.1220x over previous
#include <cuda_runtime.h>
#include <cuda_bf16.h>
#include <cuda_fp16.h>
#include <cstdint>
#include <math.h>

#define NB   8
#define HSP  37
#define WSP  37
#define NPIX 1369
#define BN   10952
#define CC   1024
#define HEADS 8
#define HD   128
#define PTS  8
#define MBLK 86
#define MPAD (MBLK * 128)   // 11008
#define NCH  16             // K chunks of 64
#define TILE_BYTES 16384    // 128 rows x 128B
#define LO_SCALE 1024.0f
#define LO_INV   0.0009765625f

#if defined(__CUDA_ARCH__) && (defined(__CUDA_ARCH_FEAT_SM103_ALL) || defined(__CUDA_ARCH_FEAT_SM100_ALL) || defined(__CUDA_ARCH_SPECIFIC__))
#define HAS_TCGEN05 1
#else
#define HAS_TCGEN05 0
#endif

#define SMEM_SWIZZLE_128B(byte_offset) ((byte_offset) ^ (((byte_offset) >> 3) & 0x70))

// ============================ Scratch ============================
__device__ float g_q[BN * CC];
__device__ float g_k[BN * CC];          // fallback path only
__device__ __half g_kh[BN * CC];        // tc path: k in fp16 for the gather
__device__ float g_off[BN * HEADS * PTS * 2];
__device__ float g_attn[BN * CC];

// Blocked+swizzled fp16 operands (16KB tiles, tile (r,c) at ((r*NCH)+c)*16KB)
// Activations: hi + lo*2^10 split. Weights q/k/out: single fp16. Woff: hi/lo split.
__device__ __half g_qh[MPAD * CC];
__device__ __half g_ql[MPAD * CC];
__device__ __half g_rh[MPAD * CC];
__device__ __half g_rl[MPAD * CC];
__device__ __half g_ah[MPAD * CC];
__device__ __half g_al[MPAD * CC];
__device__ __half g_Wq[CC * CC];
__device__ __half g_Wk[CC * CC];
__device__ __half g_Wo[CC * CC];
__device__ __half g_Wf_h[128 * CC];
__device__ __half g_Wf_l[128 * CC];

// ============================ tcgen05 helpers (guarded) ============================
#if HAS_TCGEN05
__device__ __forceinline__ uint32_t smem_to_u32(const void* p) {
    uint32_t a;
    asm("{ .reg .u64 t; cvta.to.shared.u64 t, %1; cvt.u32.u64 %0, t; }" : "=r"(a) : "l"(p));
    return a;
}
#define TCGEN05_ALLOC(smem_result_addr, nCols) \
    asm volatile("tcgen05.alloc.cta_group::1.sync.aligned.shared::cta.b32 [%0], %1;" \
        :: "r"((uint32_t)(smem_result_addr)), "r"((uint32_t)(nCols)) : "memory")
#define TCGEN05_DEALLOC(tmem_addr, nCols) \
    asm volatile("tcgen05.dealloc.cta_group::1.sync.aligned.b32 %0, %1;" :: "r"(tmem_addr), "r"(nCols))
#define TCGEN05_RELINQUISH_ALLOC_PERMIT() \
    asm volatile("tcgen05.relinquish_alloc_permit.cta_group::1.sync.aligned;")
#define TCGEN05_COMMIT_MC(mbar_smem_addr, mask) \
    asm volatile("tcgen05.commit.cta_group::1.mbarrier::arrive::one.shared::cluster.multicast::cluster.b64 [%0], %1;" \
        :: "r"((uint32_t)(mbar_smem_addr)), "h"((uint16_t)(mask)) : "memory")
#define TCGEN05_WAIT_LD() asm volatile("tcgen05.wait::ld.sync.aligned;" ::: "memory")
#define TCGEN05_FENCE_AFTER() asm volatile("tcgen05.fence::after_thread_sync;" ::: "memory")
#define TCGEN05_FENCE_BEFORE() asm volatile("tcgen05.fence::before_thread_sync;" ::: "memory")
#define MBARRIER_INIT(mbar_smem_addr, count) \
    asm volatile("mbarrier.init.shared.b64 [%0], %1;" \
        :: "r"((uint32_t)(mbar_smem_addr)), "r"((uint32_t)(count)) : "memory")
#define MBARRIER_EXPECT_TX(mbar_smem_addr, tx_bytes) \
    asm volatile("mbarrier.arrive.expect_tx.shared.b64 _, [%0], %1;" \
        :: "r"((uint32_t)(mbar_smem_addr)), "r"((uint32_t)(tx_bytes)) : "memory")
#define MBARRIER_WAIT_PARITY(mbar_smem_addr, phase_parity) do { \
    uint32_t _mbar = (uint32_t)(mbar_smem_addr); \
    uint32_t _parity = (uint32_t)(phase_parity); \
    uint32_t _done; \
    asm volatile("{\n\t.reg .pred p;\n\t" \
        "mbarrier.try_wait.parity.acquire.cta.shared::cta.b64 p, [%1], %2;\n\t" \
        "selp.b32 %0, 1, 0, p;\n\t}" : "=r"(_done) : "r"(_mbar), "r"(_parity) : "memory"); \
    if (!_done) { \
        asm volatile("{\n\t.reg .pred P1;\n\t" \
            "WAIT_LOOP_%=:\n\t" \
            "mbarrier.try_wait.parity.acquire.cta.shared::cta.b64 P1, [%0], %1, 0x989680;\n\t" \
            "@P1 bra.uni WAIT_DONE_%=;\n\t" \
            "bra.uni WAIT_LOOP_%=;\n\t" \
            "WAIT_DONE_%=:\n\t}" :: "r"(_mbar), "r"(_parity) : "memory"); \
    } \
} while(0)
#define CLUSTER_SYNC() do { \
    asm volatile("barrier.cluster.arrive.aligned;" ::: "memory"); \
    asm volatile("barrier.cluster.wait.aligned;" ::: "memory"); \
} while(0)
#define TCGEN05_LD_32X32B_X32(r, tmem_addr) \
    asm volatile("tcgen05.ld.sync.aligned.32x32b.x32.b32 " \
        "{%0, %1, %2, %3, %4, %5, %6, %7, %8, %9, %10, %11, %12, %13, %14, %15, " \
        " %16, %17, %18, %19, %20, %21, %22, %23, %24, %25, %26, %27, %28, %29, %30, %31}, [%32];" \
        : "=r"((r)[0]),  "=r"((r)[1]),  "=r"((r)[2]),  "=r"((r)[3]), \
          "=r"((r)[4]),  "=r"((r)[5]),  "=r"((r)[6]),  "=r"((r)[7]), \
          "=r"((r)[8]),  "=r"((r)[9]),  "=r"((r)[10]), "=r"((r)[11]), \
          "=r"((r)[12]), "=r"((r)[13]), "=r"((r)[14]), "=r"((r)[15]), \
          "=r"((r)[16]), "=r"((r)[17]), "=r"((r)[18]), "=r"((r)[19]), \
          "=r"((r)[20]), "=r"((r)[21]), "=r"((r)[22]), "=r"((r)[23]), \
          "=r"((r)[24]), "=r"((r)[25]), "=r"((r)[26]), "=r"((r)[27]), \
          "=r"((r)[28]), "=r"((r)[29]), "=r"((r)[30]), "=r"((r)[31]) \
        : "r"(tmem_addr))

static constexpr uint64_t SMEM_DESC_BASE_SW128 =
    (uint64_t(2)  << 61) | (uint64_t(1) << 46) | (uint64_t(64) << 32) | (uint64_t(1) << 16);
#define MAKE_SMEM_DESC(base_addr) (SMEM_DESC_BASE_SW128 | ((uint64_t)((base_addr) >> 4) & 0x3FFF))

__device__ __forceinline__ void mma_f16_ss(uint32_t d, uint64_t ad, uint64_t bd,
                                           uint32_t idesc, bool en) {
    uint32_t e = en ? 1u : 0u;
    asm volatile(
        "{\n\t.reg .pred p;\n\tsetp.ne.u32 p, %5, 0;\n\t"
        "tcgen05.mma.cta_group::1.kind::f16 [%0], %1, %2, %3, {%4, %4, %4, %4}, p;\n\t}"
        :: "r"(d), "l"(ad), "l"(bd), "r"(idesc), "r"(0u), "r"(e) : "memory");
}
__device__ __forceinline__ void bulk_g2s(uint32_t dst, const void* src, uint32_t bytes, uint32_t mbar) {
    asm volatile("cp.async.bulk.shared::cluster.global.mbarrier::complete_tx::bytes [%0], [%1], %2, [%3];"
        :: "r"(dst), "l"(src), "r"(bytes), "r"(mbar) : "memory");
}
__device__ __forceinline__ void bulk_g2s_mc(uint32_t dst, const void* src, uint32_t bytes,
                                            uint32_t mbar, uint16_t mask) {
    asm volatile("cp.async.bulk.shared::cluster.global.mbarrier::complete_tx::bytes.multicast::cluster [%0], [%1], %2, [%3], %4;"
        :: "r"(dst), "l"(src), "r"(bytes), "r"(mbar), "h"(mask) : "memory");
}
__device__ __forceinline__ uint32_t cluster_rank() {
    uint32_t r;
    asm("mov.u32 %0, %%cluster_ctarank;" : "=r"(r));
    return r;
}
#endif  // HAS_TCGEN05

// ============================ Pack kernels ============================
// Activations fp32 row-major [M,1024] -> blocked swizzled fp16 hi / (lo*2^10) tiles.
__global__ void split_act2_kernel(const float* __restrict__ src0,
                                  __half* __restrict__ hi0, __half* __restrict__ lo0,
                                  const float* __restrict__ src1,
                                  __half* __restrict__ hi1, __half* __restrict__ lo1, int M)
{
    const float* src = blockIdx.z ? src1 : src0;
    __half* hi = blockIdx.z ? hi1 : hi0;
    __half* lo = blockIdx.z ? lo1 : lo0;
    const int c  = blockIdx.x;
    const int mb = blockIdx.y;
    const int t  = threadIdx.x;
    const int j  = t & 7;
    char* hbase = (char*)hi + ((size_t)(mb * NCH + c)) * TILE_BYTES;
    char* lbase = (char*)lo + ((size_t)(mb * NCH + c)) * TILE_BYTES;

    #pragma unroll
    for (int g = 0; g < 8; g++) {
        int ml = g * 16 + (t >> 3);
        int m = mb * 128 + ml;
        float x[8];
        if (m < M) {
            float4 a = *(const float4*)(src + (size_t)m * CC + c * 64 + j * 8);
            float4 b = *(const float4*)(src + (size_t)m * CC + c * 64 + j * 8 + 4);
            x[0]=a.x; x[1]=a.y; x[2]=a.z; x[3]=a.w; x[4]=b.x; x[5]=b.y; x[6]=b.z; x[7]=b.w;
        } else {
            #pragma unroll
            for (int i = 0; i < 8; i++) x[i] = 0.0f;
        }
        __half h[8], l[8];
        #pragma unroll
        for (int i = 0; i < 8; i++) {
            h[i] = __float2half(x[i]);
            l[i] = __float2half((x[i] - __half2float(h[i])) * LO_SCALE);
        }
        uint32_t off = SMEM_SWIZZLE_128B((uint32_t)(ml * 128 + j * 16));
        *(uint4*)(hbase + off) = *(uint4*)h;
        *(uint4*)(lbase + off) = *(uint4*)l;
    }
}

// All 4 weights in one launch: grid (NCH, 25), block 512.
// y: [0,8) Wq single, [8,16) Wkv single, 16 Woff hi+lo, [17,25) Wout single.
__global__ void __launch_bounds__(512)
pack_weights_all(const float* __restrict__ Wq, const float* __restrict__ Wkv,
                 const float* __restrict__ Woff, const float* __restrict__ Wout,
                 __half* __restrict__ wq, __half* __restrict__ wk,
                 __half* __restrict__ wfh, __half* __restrict__ wfl,
                 __half* __restrict__ wo)
{
    __shared__ float ts[64][129];
    const int c = blockIdx.x;
    const int y = blockIdx.y;
    const int t = threadIdx.x;

    const float* W; int ldw, nb; __half *hi, *lo;
    if (y < 8)       { W = Wq;   ldw = CC;     nb = y;      hi = wq;  lo = nullptr; }
    else if (y < 16) { W = Wkv;  ldw = 2 * CC; nb = y - 8;  hi = wk;  lo = nullptr; }
    else if (y < 17) { W = Woff; ldw = 128;    nb = 0;      hi = wfh; lo = wfl; }
    else             { W = Wout; ldw = CC;     nb = y - 17; hi = wo;  lo = nullptr; }

    const int k0 = c * 64;
    const int n0 = nb * 128;
    const int lrow = t >> 7;
    const int lcol = t & 127;
    #pragma unroll
    for (int i = 0; i < 16; i++) {
        int row = i * 4 + lrow;
        ts[row][lcol] = W[(size_t)(k0 + row) * ldw + n0 + lcol];
    }
    __syncthreads();

    char* hbase = (char*)hi + ((size_t)(nb * NCH + c)) * TILE_BYTES;
    char* lbase = lo ? (char*)lo + ((size_t)(nb * NCH + c)) * TILE_BYTES : nullptr;
    #pragma unroll
    for (int it = 0; it < 2; it++) {
        int idx = t + it * 512;
        int nl = idx >> 3;
        int j  = idx & 7;
        __half h[8], l[8];
        #pragma unroll
        for (int jj = 0; jj < 8; jj++) {
            float x = ts[j * 8 + jj][nl];
            h[jj] = __float2half(x);
            l[jj] = __float2half((x - __half2float(h[jj])) * LO_SCALE);
        }
        uint32_t off = SMEM_SWIZZLE_128B((uint32_t)(nl * 128 + j * 16));
        *(uint4*)(hbase + off) = *(uint4*)h;
        if (lbase) *(uint4*)(lbase + off) = *(uint4*)l;
    }
}

// ===== tcgen05 GEMM: fp16, A hi/lo split (lo*2^10 -> second accumulator), =====
// ===== optional B hi/lo, 3-stage bulk-async pipeline, cluster-2 B multicast ===
// BPARTS=1: passes ah*b -> acc0, al*b -> acc1.   (8 MMAs/chunk)
// BPARTS=2: + ah*bl -> acc1 (bl also *2^10).     (12 MMAs/chunk)
// Epilogue: C = acc0 + acc1 * 2^-10 + bias.
template <int NT, int BPARTS, typename TOut>
__global__ void __launch_bounds__(128, 1) __cluster_dims__(1, 2, 1)
gemm_tc(const char* __restrict__ Ah, const char* __restrict__ Al,
        const char* __restrict__ Bh, const char* __restrict__ Bl,
        const float* __restrict__ bias, TOut* __restrict__ C, int M, int Ncols)
{
#if HAS_TCGEN05
    constexpr int NBB = NT / 128;
    constexpr int NBT = BPARTS * NBB;                 // B tiles per chunk
    constexpr uint32_t SB = (2 + NBT) * TILE_BYTES;   // stage bytes
    constexpr uint32_t HDR = 1024;
    constexpr uint32_t IDESC = 0x8000010u | ((NT / 8) << 17);  // fp16 x fp16, f32 acc

    extern __shared__ char smem[];
    uint32_t sb = smem_to_u32(smem);
    const int tid = threadIdx.x;
    const int wid = tid >> 5;
    const int lane = tid & 31;
    const int m0 = blockIdx.y * 128;
    const int n0 = blockIdx.x * NT;
    const uint32_t rank = cluster_rank();

    if (wid == 0) TCGEN05_ALLOC(sb + 0, 512);
    if (tid == 0) {
        MBARRIER_INIT(sb + 16, 1);  // full0
        MBARRIER_INIT(sb + 24, 1);  // full1
        MBARRIER_INIT(sb + 32, 1);  // full2
        MBARRIER_INIT(sb + 48, 2);  // empty0 (both ranks' commits)
        MBARRIER_INIT(sb + 56, 2);  // empty1
        MBARRIER_INIT(sb + 64, 2);  // empty2
    }
    __syncthreads();
    CLUSTER_SYNC();
    uint32_t tmem;
    asm volatile("ld.shared.b32 %0, [%1];" : "=r"(tmem) : "r"(sb));

    if (tid == 0) {
        auto issue = [&](int c) {
            int s = c % 3;
            uint32_t fb = sb + 16 + 8u * s;
            uint32_t st = sb + HDR + (uint32_t)s * SB;
            MBARRIER_EXPECT_TX(fb, SB);
            size_t aoff = ((size_t)blockIdx.y * NCH + c) * TILE_BYTES;
            bulk_g2s(st, Ah + aoff, TILE_BYTES, fb);
            bulk_g2s(st + TILE_BYTES, Al + aoff, TILE_BYTES, fb);
            #pragma unroll
            for (int i = 0; i < NBT; i++) {
                const char* src;
                if (BPARTS == 1)
                    src = Bh + ((size_t)(blockIdx.x * NBB + i) * NCH + c) * TILE_BYTES;
                else
                    src = (i == 0 ? Bh : Bl) + ((size_t)(blockIdx.x * NBB) * NCH + c) * TILE_BYTES;
                if ((uint32_t)(i & 1) == rank)
                    bulk_g2s_mc(st + (2 + i) * TILE_BYTES, src, TILE_BYTES, fb, 3);
            }
        };
        issue(0); issue(1); issue(2);
        for (int c = 0; c < NCH; c++) {
            int s = c % 3;
            uint32_t fullb  = sb + 16 + 8u * s;
            uint32_t emptyb = sb + 48 + 8u * s;
            MBARRIER_WAIT_PARITY(fullb, (uint32_t)((c / 3) & 1));
            uint32_t st = sb + HDR + (uint32_t)s * SB;
            uint64_t ahd = MAKE_SMEM_DESC(st);
            uint64_t ald = MAKE_SMEM_DESC(st + TILE_BYTES);
            uint64_t bhd = MAKE_SMEM_DESC(st + 2 * TILE_BYTES);
            #pragma unroll
            for (int ks = 0; ks < 4; ks++)
                mma_f16_ss(tmem, ahd + ks * 2, bhd + ks * 2, IDESC, !(c == 0 && ks == 0));
            #pragma unroll
            for (int ks = 0; ks < 4; ks++)
                mma_f16_ss(tmem + NT, ald + ks * 2, bhd + ks * 2, IDESC, !(c == 0 && ks == 0));
            if (BPARTS == 2) {
                uint64_t bld = MAKE_SMEM_DESC(st + 3 * TILE_BYTES);
                #pragma unroll
                for (int ks = 0; ks < 4; ks++)
                    mma_f16_ss(tmem + NT, ahd + ks * 2, bld + ks * 2, IDESC, true);
            }
            TCGEN05_COMMIT_MC(emptyb, 3);
            if (c + 3 < NCH) {
                MBARRIER_WAIT_PARITY(emptyb, (uint32_t)((c / 3) & 1));
                issue(c + 3);
            }
        }
        for (int c = NCH - 3; c < NCH; c++)
            MBARRIER_WAIT_PARITY(sb + 48 + 8u * (c % 3), (uint32_t)((c / 3) & 1));
    }
    __syncthreads();
    TCGEN05_FENCE_AFTER();

    // Epilogue: combine acc0 + acc1*2^-10, per-warp transpose, coalesced STG.
    float* buf = (float*)(smem + HDR) + wid * (32 * 33);
    #pragma unroll
    for (int base = 0; base < NT; base += 32) {
        uint32_t r0[32], r1[32];
        TCGEN05_LD_32X32B_X32(r0, tmem + base);
        TCGEN05_LD_32X32B_X32(r1, tmem + NT + base);
        TCGEN05_WAIT_LD();
        #pragma unroll
        for (int q = 0; q < 32; q++)
            buf[lane * 33 + q] = __uint_as_float(r0[q]) + __uint_as_float(r1[q]) * LO_INV;
        __syncwarp();
        float bv = bias[n0 + base + lane];
        #pragma unroll 4
        for (int rr = 0; rr < 32; rr++) {
            int gm = m0 + wid * 32 + rr;
            if (gm < M)
                C[(size_t)gm * Ncols + n0 + base + lane] = (TOut)(buf[rr * 33 + lane] + bv);
        }
        __syncwarp();
    }
    TCGEN05_FENCE_BEFORE();
    __syncthreads();
    if (wid == 0) {
        TCGEN05_RELINQUISH_ALLOC_PERMIT();
        TCGEN05_DEALLOC(tmem, 512);
    }
#endif
}

// ============================ Fallback SGEMM ============================
__global__ void sgemm_bias_kernel(const float* __restrict__ A,
                                  const float* __restrict__ Wt,
                                  const float* __restrict__ bias,
                                  float* __restrict__ C,
                                  int M, int Ncols, int K, int ldw)
{
    __shared__ float As[16][64];
    __shared__ float Bs[16][64];
    const int tid = threadIdx.x;
    const int tx = tid & 15;
    const int ty = tid >> 4;
    const int n0 = blockIdx.x * 64;
    const int m0 = blockIdx.y * 64;
    float acc[4][4] = {};
    for (int k0 = 0; k0 < K; k0 += 16) {
        #pragma unroll
        for (int i = 0; i < 4; i++) {
            int idx = tid + i * 256;
            int m  = idx >> 4, kk = idx & 15, gm = m0 + m;
            As[kk][m] = (gm < M) ? A[(size_t)gm * K + (k0 + kk)] : 0.0f;
        }
        #pragma unroll
        for (int i = 0; i < 4; i++) {
            int idx = tid + i * 256;
            int kk = idx >> 6, n = idx & 63, gn = n0 + n;
            Bs[kk][n] = (gn < Ncols) ? Wt[(size_t)(k0 + kk) * ldw + gn] : 0.0f;
        }
        __syncthreads();
        #pragma unroll
        for (int kk = 0; kk < 16; kk++) {
            float4 a = *(const float4*)&As[kk][ty * 4];
            float4 w = *(const float4*)&Bs[kk][tx * 4];
            acc[0][0] += a.x*w.x; acc[0][1] += a.x*w.y; acc[0][2] += a.x*w.z; acc[0][3] += a.x*w.w;
            acc[1][0] += a.y*w.x; acc[1][1] += a.y*w.y; acc[1][2] += a.y*w.z; acc[1][3] += a.y*w.w;
            acc[2][0] += a.z*w.x; acc[2][1] += a.z*w.y; acc[2][2] += a.z*w.z; acc[2][3] += a.z*w.w;
            acc[3][0] += a.w*w.x; acc[3][1] += a.w*w.y; acc[3][2] += a.w*w.z; acc[3][3] += a.w*w.w;
        }
        __syncthreads();
    }
    #pragma unroll
    for (int r = 0; r < 4; r++) {
        int gm = m0 + ty * 4 + r;
        if (gm >= M) continue;
        #pragma unroll
        for (int c = 0; c < 4; c++) {
            int gn = n0 + tx * 4 + c;
            if (gn < Ncols) C[(size_t)gm * Ncols + gn] = acc[r][c] + bias[gn];
        }
    }
}

// ============================ Attention (warp per (bn,h)), fp16 k gathers ============
__global__ void attn_warp_kernel()
{
    const int bn = blockIdx.x;
    const int h  = threadIdx.x >> 5;
    const int lane = threadIdx.x & 31;

    const int b = bn / NPIX;
    const int n = bn % NPIX;
    const int row = n / WSP;
    const int col = n % WSP;
    const float step = 2.0f / 36.0f;
    const float ybase = -1.0f + row * step;
    const float xbase = -1.0f + col * step;

    float4 q4 = *(const float4*)(g_q + (size_t)bn * CC + h * HD + lane * 4);
    const __half* kbase = g_kh + (size_t)b * NPIX * CC + h * HD + lane * 4;

    float offv = 0.0f;
    if (lane < 16) offv = g_off[(size_t)bn * (HEADS * PTS * 2) + h * (PTS * 2) + lane];

    float4 sv[PTS];
    float sc[PTS];
    #pragma unroll
    for (int p = 0; p < PTS; p++) {
        float o0 = __shfl_sync(0xffffffffu, offv, 2 * p);
        float o1 = __shfl_sync(0xffffffffu, offv, 2 * p + 1);
        float xn = ybase + o0;
        float yn = xbase + o1;
        float ix = fminf(fmaxf((xn + 1.0f) * 0.5f * (WSP - 1), 0.0f), (float)(WSP - 1));
        float iy = fminf(fmaxf((yn + 1.0f) * 0.5f * (HSP - 1), 0.0f), (float)(HSP - 1));
        float x0f = floorf(ix), y0f = floorf(iy);
        float wx = ix - x0f, wy = iy - y0f;
        int x0 = (int)x0f, y0 = (int)y0f;
        int x1 = min(x0 + 1, WSP - 1);
        int y1 = min(y0 + 1, HSP - 1);

        uint2 u00 = *(const uint2*)(kbase + (size_t)(y0 * WSP + x0) * CC);
        uint2 u01 = *(const uint2*)(kbase + (size_t)(y0 * WSP + x1) * CC);
        uint2 u10 = *(const uint2*)(kbase + (size_t)(y1 * WSP + x0) * CC);
        uint2 u11 = *(const uint2*)(kbase + (size_t)(y1 * WSP + x1) * CC);
        float2 a00 = __half22float2(*(__half2*)&u00.x), b00 = __half22float2(*(__half2*)&u00.y);
        float2 a01 = __half22float2(*(__half2*)&u01.x), b01 = __half22float2(*(__half2*)&u01.y);
        float2 a10 = __half22float2(*(__half2*)&u10.x), b10 = __half22float2(*(__half2*)&u10.y);
        float2 a11 = __half22float2(*(__half2*)&u11.x), b11 = __half22float2(*(__half2*)&u11.y);

        float w00 = (1.0f - wy) * (1.0f - wx), w01 = (1.0f - wy) * wx;
        float w10 = wy * (1.0f - wx), w11 = wy * wx;
        float4 s;
        s.x = w00*a00.x + w01*a01.x + w10*a10.x + w11*a11.x;
        s.y = w00*a00.y + w01*a01.y + w10*a10.y + w11*a11.y;
        s.z = w00*b00.x + w01*b01.x + w10*b10.x + w11*b11.x;
        s.w = w00*b00.y + w01*b01.y + w10*b10.y + w11*b11.y;
        sv[p] = s;

        float d = q4.x*s.x + q4.y*s.y + q4.z*s.z + q4.w*s.w;
        #pragma unroll
        for (int o = 16; o; o >>= 1) d += __shfl_xor_sync(0xffffffffu, d, o);
        sc[p] = d * 0.088388347648318447f;
    }

    float m = sc[0];
    #pragma unroll
    for (int p = 1; p < PTS; p++) m = fmaxf(m, sc[p]);
    float e[PTS], denom = 0.0f;
    #pragma unroll
    for (int p = 0; p < PTS; p++) { e[p] = expf(sc[p] - m); denom += e[p]; }
    float inv = 1.0f / denom;

    float4 o = make_float4(0, 0, 0, 0);
    #pragma unroll
    for (int p = 0; p < PTS; p++) {
        float w = e[p] * inv;
        o.x += w * sv[p].x; o.y += w * sv[p].y; o.z += w * sv[p].z; o.w += w * sv[p].w;
    }

    int k = h * HD + lane * 4;
    int mb = bn >> 7, ml = bn & 127;
    int c = k >> 6, kl = k & 63;
    size_t tbase = ((size_t)(mb * NCH + c)) * TILE_BYTES;
    uint32_t off = SMEM_SWIZZLE_128B((uint32_t)(ml * 128 + kl * 2));

    __half h4[4], l4[4];
    float ov[4] = {o.x, o.y, o.z, o.w};
    #pragma unroll
    for (int i = 0; i < 4; i++) {
        h4[i] = __float2half(ov[i]);
        l4[i] = __float2half((ov[i] - __half2float(h4[i])) * LO_SCALE);
    }
    *(uint2*)((char*)g_ah + tbase + off) = *(uint2*)h4;
    *(uint2*)((char*)g_al + tbase + off) = *(uint2*)l4;
}

// Fallback attention (fp32 k, fp32 output to g_attn)
__global__ void attn_kernel(float* __restrict__ out)
{
    const int bn = blockIdx.x;
    const int h  = blockIdx.y;
    const int t  = threadIdx.x;
    const int lane = t & 31;
    const int wid  = t >> 5;
    const int b = bn / NPIX;
    const int n = bn % NPIX;
    const int row = n / WSP;
    const int col = n % WSP;
    const float step = 2.0f / 36.0f;
    const float ybase = -1.0f + row * step;
    const float xbase = -1.0f + col * step;
    const float qv = g_q[(size_t)bn * CC + h * HD + t];
    const float* kbase = g_k + (size_t)b * NPIX * CC + h * HD + t;
    const float* offp  = g_off + (size_t)bn * (HEADS * PTS * 2) + h * (PTS * 2);
    float sv[PTS];
    __shared__ float red[PTS][4];
    __shared__ float sc[PTS];
    #pragma unroll
    for (int p = 0; p < PTS; p++) {
        float o0 = offp[p * 2 + 0], o1 = offp[p * 2 + 1];
        float xn = ybase + o0, yn = xbase + o1;
        float ix = fminf(fmaxf((xn + 1.0f) * 0.5f * (WSP - 1), 0.0f), (float)(WSP - 1));
        float iy = fminf(fmaxf((yn + 1.0f) * 0.5f * (HSP - 1), 0.0f), (float)(HSP - 1));
        float x0f = floorf(ix), y0f = floorf(iy);
        float wx = ix - x0f, wy = iy - y0f;
        int x0 = (int)x0f, y0 = (int)y0f;
        int x1 = min(x0 + 1, WSP - 1), y1 = min(y0 + 1, HSP - 1);
        float v00 = kbase[(size_t)(y0 * WSP + x0) * CC];
        float v01 = kbase[(size_t)(y0 * WSP + x1) * CC];
        float v10 = kbase[(size_t)(y1 * WSP + x0) * CC];
        float v11 = kbase[(size_t)(y1 * WSP + x1) * CC];
        float s = (1.0f - wy) * ((1.0f - wx) * v00 + wx * v01)
                +          wy * ((1.0f - wx) * v10 + wx * v11);
        sv[p] = s;
        float d = qv * s;
        #pragma unroll
        for (int o = 16; o; o >>= 1) d += __shfl_down_sync(0xffffffffu, d, o);
        if (lane == 0) red[p][wid] = d;
    }
    __syncthreads();
    if (t < PTS) sc[t] = (red[t][0] + red[t][1] + red[t][2] + red[t][3]) * 0.088388347648318447f;
    __syncthreads();
    float m = sc[0];
    #pragma unroll
    for (int p = 1; p < PTS; p++) m = fmaxf(m, sc[p]);
    float e[PTS], denom = 0.0f;
    #pragma unroll
    for (int p = 0; p < PTS; p++) { e[p] = expf(sc[p] - m); denom += e[p]; }
    float inv = 1.0f / denom;
    float o = 0.0f;
    #pragma unroll
    for (int p = 0; p < PTS; p++) o += e[p] * inv * sv[p];
    out[(size_t)bn * CC + h * HD + t] = o;
}

// ============================ Launch ============================
extern "C" void kernel_launch(void* const* d_in, const int* in_sizes, int n_in,
                              void* d_out, int out_size)
{
    const float* query = (const float*)d_in[0];
    const float* ref   = (const float*)d_in[1];
    const float* Wq    = (const float*)d_in[2];
    const float* bq    = (const float*)d_in[3];
    const float* Wkv   = (const float*)d_in[4];
    const float* bkv   = (const float*)d_in[5];
    const float* Woff  = (const float*)d_in[6];
    const float* boff  = (const float*)d_in[7];
    const float* Wout  = (const float*)d_in[8];
    const float* bout  = (const float*)d_in[9];
    float* out = (float*)d_out;

    float *q_ptr, *k_ptr, *off_ptr, *attn_ptr;
    __half* kh_ptr;
    cudaGetSymbolAddress((void**)&q_ptr,    g_q);
    cudaGetSymbolAddress((void**)&k_ptr,    g_k);
    cudaGetSymbolAddress((void**)&kh_ptr,   g_kh);
    cudaGetSymbolAddress((void**)&off_ptr,  g_off);
    cudaGetSymbolAddress((void**)&attn_ptr, g_attn);

    cudaFuncAttributes fa;
    cudaFuncGetAttributes(&fa, gemm_tc<256, 1, float>);
    bool use_tc = (fa.numRegs > 32);

    if (use_tc) {
        char *qh, *ql, *rh, *rl, *ah, *al;
        char *wq, *wk, *wo, *wfh, *wfl;
        cudaGetSymbolAddress((void**)&qh, g_qh);   cudaGetSymbolAddress((void**)&ql, g_ql);
        cudaGetSymbolAddress((void**)&rh, g_rh);   cudaGetSymbolAddress((void**)&rl, g_rl);
        cudaGetSymbolAddress((void**)&ah, g_ah);   cudaGetSymbolAddress((void**)&al, g_al);
        cudaGetSymbolAddress((void**)&wq, g_Wq);
        cudaGetSymbolAddress((void**)&wk, g_Wk);
        cudaGetSymbolAddress((void**)&wo, g_Wo);
        cudaGetSymbolAddress((void**)&wfh, g_Wf_h); cudaGetSymbolAddress((void**)&wfl, g_Wf_l);

        static bool attr_set = false;
        if (!attr_set) {
            cudaFuncSetAttribute(gemm_tc<256, 1, float>,  cudaFuncAttributeMaxDynamicSharedMemorySize, 197632);
            cudaFuncSetAttribute(gemm_tc<256, 1, __half>, cudaFuncAttributeMaxDynamicSharedMemorySize, 197632);
            cudaFuncSetAttribute(gemm_tc<128, 2, float>,  cudaFuncAttributeMaxDynamicSharedMemorySize, 197632);
            attr_set = true;
        }

        split_act2_kernel<<<dim3(NCH, MBLK, 2), 128>>>(
            query, (__half*)qh, (__half*)ql,
            ref,   (__half*)rh, (__half*)rl, BN);
        pack_weights_all<<<dim3(NCH, 25), 512>>>(
            Wq, Wkv, Woff, Wout,
            (__half*)wq, (__half*)wk, (__half*)wfh, (__half*)wfl, (__half*)wo);

        gemm_tc<256, 1, float ><<<dim3(4, MBLK), 128, 197632>>>(qh, ql, wq, nullptr, bq,   q_ptr,   BN, CC);
        gemm_tc<256, 1, __half><<<dim3(4, MBLK), 128, 197632>>>(rh, rl, wk, nullptr, bkv,  kh_ptr,  BN, CC);
        gemm_tc<128, 2, float ><<<dim3(1, MBLK), 128, 197632>>>(qh, ql, wfh, wfl,    boff, off_ptr, BN, 128);

        attn_warp_kernel<<<BN, 256>>>();

        gemm_tc<256, 1, float><<<dim3(4, MBLK), 128, 197632>>>(ah, al, wo, nullptr, bout, out, BN, CC);
    } else {
        dim3 blk(256);
        dim3 gBig((CC + 63) / 64, (BN + 63) / 64);
        dim3 gOff((128 + 63) / 64, (BN + 63) / 64);
        sgemm_bias_kernel<<<gBig, blk>>>(query, Wq, bq, q_ptr, BN, CC, CC, CC);
        sgemm_bias_kernel<<<gBig, blk>>>(ref, Wkv, bkv, k_ptr, BN, CC, CC, 2 * CC);
        sgemm_bias_kernel<<<gOff, blk>>>(query, Woff, boff, off_ptr, BN, HEADS * PTS * 2, CC, HEADS * PTS * 2);
        attn_kernel<<<dim3(BN, HEADS), 128>>>(attn_ptr);
        sgemm_bias_kernel<<<gBig, blk>>>(attn_ptr, Wout, bout, out, BN, CC, CC, CC);
    }
}